// round 2
// baseline (speedup 1.0000x reference)
#include <cuda_runtime.h>
#include <math.h>
#include <cstdint>

// Problem dims (fixed for this dataset entry)
#define Bb 4
#define Ss 4096
#define Dd 1024
#define Nn 256
#define Mm (Bb*Ss)            // 16384 tokens
#define CHUNK 64
#define NCHUNK (Ss/CHUNK)     // 64

// Scratch (allocations are forbidden; use device globals)
__device__ float g_x[(size_t)Mm*Dd];        // 64 MB  rmsnormed tokens
__device__ float g_u[(size_t)Mm*Nn];        // 16 MB  input projection
__device__ float g_states[(size_t)Mm*Nn];   // 16 MB  scan states
__device__ float g_loc[Bb*NCHUNK*Nn];       // chunk-local final states
__device__ float g_init[Bb*NCHUNK*Nn];      // chunk initial states
__device__ float g_decay[Nn];
__device__ float g_decayL[Nn];              // decay^CHUNK

// ---------------------------------------------------------------------------
// decay = sigmoid(log_decay); decayL = decay^64 (6 squarings)
__global__ void k_decay(const float* __restrict__ log_decay) {
    int n = threadIdx.x;
    float d = 1.0f / (1.0f + expf(-log_decay[n]));
    g_decay[n] = d;
    float p = d;
    #pragma unroll
    for (int i = 0; i < 6; i++) p *= p;
    g_decayL[n] = p;
}

// ---------------------------------------------------------------------------
// RMSNorm: one block per token, 256 threads, float4
__global__ void __launch_bounds__(256) k_rmsnorm(const float* __restrict__ tokens,
                                                 const float* __restrict__ norm_w) {
    int t = blockIdx.x;
    const float4* tp = (const float4*)(tokens + (size_t)t * Dd);
    float4 v = tp[threadIdx.x];
    float ss = v.x*v.x + v.y*v.y + v.z*v.z + v.w*v.w;
    #pragma unroll
    for (int o = 16; o > 0; o >>= 1) ss += __shfl_xor_sync(0xffffffffu, ss, o);
    __shared__ float wsum[8];
    int wid = threadIdx.x >> 5, lane = threadIdx.x & 31;
    if (lane == 0) wsum[wid] = ss;
    __syncthreads();
    float tot = 0.f;
    #pragma unroll
    for (int i = 0; i < 8; i++) tot += wsum[i];
    float scale = rsqrtf(tot * (1.0f / Dd) + 1e-4f);
    float4 w = ((const float4*)norm_w)[threadIdx.x];
    float4 o;
    o.x = v.x * scale * w.x;
    o.y = v.y * scale * w.y;
    o.z = v.z * scale * w.z;
    o.w = v.w * scale * w.w;
    ((float4*)(g_x + (size_t)t * Dd))[threadIdx.x] = o;
}

// ---------------------------------------------------------------------------
// SGEMM: C[m,n] = sum_k A[m,k]*Bw[n,k]  (+ bias0[n]) (+ bias1[n]) (+ src[m,n])
// A row-major [M,K], Bw row-major [N,K]. 128x128 tile, BK=8, 8x8 per thread.
// Register-prefetch double buffering on the global loads.
// All dims here are multiples of 128 (M/N) and 8 (K); no bounds checks.
__global__ void __launch_bounds__(256) k_gemm(
    const float* __restrict__ A, const float* __restrict__ Bw,
    float* __restrict__ C, const float* __restrict__ src,
    const float* __restrict__ bias0, const float* __restrict__ bias1,
    int M, int N, int K)
{
    __shared__ float As[8][128];
    __shared__ float Bs[8][128];
    const int tid = threadIdx.x;
    const int m0 = blockIdx.y * 128;
    const int n0 = blockIdx.x * 128;
    const int tx = tid & 15;          // col group
    const int ty = tid >> 4;          // row group
    const int lrow = tid >> 1;        // 0..127 (tile row to load)
    const int lcol = (tid & 1) * 4;   // 0 or 4 (k offset)
    const float* Ap = A + (size_t)(m0 + lrow) * K + lcol;
    const float* Bp = Bw + (size_t)(n0 + lrow) * K + lcol;

    float acc[8][8];
    #pragma unroll
    for (int i = 0; i < 8; i++)
        #pragma unroll
        for (int j = 0; j < 8; j++) acc[i][j] = 0.f;

    float4 av = *(const float4*)(Ap);
    float4 bv = *(const float4*)(Bp);

    for (int k0 = 0; k0 < K; k0 += 8) {
        As[lcol+0][lrow] = av.x; As[lcol+1][lrow] = av.y;
        As[lcol+2][lrow] = av.z; As[lcol+3][lrow] = av.w;
        Bs[lcol+0][lrow] = bv.x; Bs[lcol+1][lrow] = bv.y;
        Bs[lcol+2][lrow] = bv.z; Bs[lcol+3][lrow] = bv.w;
        __syncthreads();
        // prefetch next k-tile while computing this one
        if (k0 + 8 < K) {
            av = *(const float4*)(Ap + k0 + 8);
            bv = *(const float4*)(Bp + k0 + 8);
        }
        #pragma unroll
        for (int k = 0; k < 8; k++) {
            float a[8], b[8];
            *(float4*)(a+0) = *(const float4*)&As[k][ty*8+0];
            *(float4*)(a+4) = *(const float4*)&As[k][ty*8+4];
            *(float4*)(b+0) = *(const float4*)&Bs[k][tx*8+0];
            *(float4*)(b+4) = *(const float4*)&Bs[k][tx*8+4];
            #pragma unroll
            for (int i = 0; i < 8; i++)
                #pragma unroll
                for (int j = 0; j < 8; j++)
                    acc[i][j] = fmaf(a[i], b[j], acc[i][j]);
        }
        __syncthreads();
    }

    float4 bb0a = make_float4(0,0,0,0), bb0b = make_float4(0,0,0,0);
    float4 bb1a = make_float4(0,0,0,0), bb1b = make_float4(0,0,0,0);
    if (bias0) { bb0a = *(const float4*)&bias0[n0+tx*8]; bb0b = *(const float4*)&bias0[n0+tx*8+4]; }
    if (bias1) { bb1a = *(const float4*)&bias1[n0+tx*8]; bb1b = *(const float4*)&bias1[n0+tx*8+4]; }

    #pragma unroll
    for (int i = 0; i < 8; i++) {
        size_t row = (size_t)(m0 + ty*8 + i) * N + n0 + tx*8;
        float4 o0 = make_float4(acc[i][0], acc[i][1], acc[i][2], acc[i][3]);
        float4 o1 = make_float4(acc[i][4], acc[i][5], acc[i][6], acc[i][7]);
        if (bias0) {
            o0.x += bb0a.x; o0.y += bb0a.y; o0.z += bb0a.z; o0.w += bb0a.w;
            o1.x += bb0b.x; o1.y += bb0b.y; o1.z += bb0b.z; o1.w += bb0b.w;
        }
        if (bias1) {
            o0.x += bb1a.x; o0.y += bb1a.y; o0.z += bb1a.z; o0.w += bb1a.w;
            o1.x += bb1b.x; o1.y += bb1b.y; o1.z += bb1b.z; o1.w += bb1b.w;
        }
        if (src) {
            float4 s0 = *(const float4*)&src[row];
            float4 s1 = *(const float4*)&src[row+4];
            o0.x += s0.x; o0.y += s0.y; o0.z += s0.z; o0.w += s0.w;
            o1.x += s1.x; o1.y += s1.y; o1.z += s1.z; o1.w += s1.w;
        }
        *(float4*)&C[row]   = o0;
        *(float4*)&C[row+4] = o1;
    }
}

// ---------------------------------------------------------------------------
// Chunked linear scan: state_t = decay*state_{t-1} + u_t
// Pass 1: per-chunk local scan from zero init -> chunk-final local state
__global__ void __launch_bounds__(256) k_scan1() {
    int c = blockIdx.x, b = blockIdx.y, n = threadIdx.x;
    float d = g_decay[n];
    const float* up = g_u + ((size_t)(b*Ss + c*CHUNK)) * Nn + n;
    float s = 0.f;
    #pragma unroll 8
    for (int t = 0; t < CHUNK; t++) s = fmaf(d, s, up[(size_t)t * Nn]);
    g_loc[(b*NCHUNK + c)*Nn + n] = s;
}

// Pass 2: exclusive scan over chunk carries (1024 independent chains, 64 steps)
__global__ void k_scan2() {
    int idx = threadIdx.x + blockIdx.x * blockDim.x;   // <<<4,256>>> -> 1024
    int b = idx >> 8, n = idx & 255;
    float dL = g_decayL[n];
    float init = 0.f;
    for (int c = 0; c < NCHUNK; c++) {
        g_init[(b*NCHUNK + c)*Nn + n] = init;
        init = fmaf(dL, init, g_loc[(b*NCHUNK + c)*Nn + n]);
    }
}

// Pass 3: rescan chunks with correct init, write all states
__global__ void __launch_bounds__(256) k_scan3() {
    int c = blockIdx.x, b = blockIdx.y, n = threadIdx.x;
    float d = g_decay[n];
    size_t base = ((size_t)(b*Ss + c*CHUNK)) * Nn + n;
    float s = g_init[(b*NCHUNK + c)*Nn + n];
    #pragma unroll 8
    for (int t = 0; t < CHUNK; t++) {
        s = fmaf(d, s, g_u[base + (size_t)t * Nn]);
        g_states[base + (size_t)t * Nn] = s;
    }
}

// ---------------------------------------------------------------------------
extern "C" void kernel_launch(void* const* d_in, const int* in_sizes, int n_in,
                              void* d_out, int out_size)
{
    const float* tokens    = (const float*)d_in[0];
    const float* norm_w    = (const float*)d_in[1];
    const float* W_in      = (const float*)d_in[2];
    const float* b_in      = (const float*)d_in[3];
    const float* W_out     = (const float*)d_in[4];
    const float* b_out     = (const float*)d_in[5];
    const float* W_skip    = (const float*)d_in[6];
    const float* b_skip    = (const float*)d_in[7];
    const float* log_decay = (const float*)d_in[8];
    float* out = (float*)d_out;

    void *px = nullptr, *pu = nullptr, *ps = nullptr;
    cudaGetSymbolAddress(&px, g_x);
    cudaGetSymbolAddress(&pu, g_u);
    cudaGetSymbolAddress(&ps, g_states);
    float* x  = (float*)px;
    float* u  = (float*)pu;
    float* st = (float*)ps;

    // 1) decay precompute
    k_decay<<<1, Nn>>>(log_decay);

    // 2) RMSNorm -> g_x
    k_rmsnorm<<<Mm, 256>>>(tokens, norm_w);

    // 3) u = x @ W_in^T + b_in   [16384 x 256], K=1024
    {
        dim3 g(Nn/128, Mm/128);
        k_gemm<<<g, 256>>>(x, W_in, u, nullptr, b_in, nullptr, Mm, Nn, Dd);
    }

    // 4-6) chunked scan -> g_states
    {
        dim3 g(NCHUNK, Bb);
        k_scan1<<<g, 256>>>();
        k_scan2<<<4, 256>>>();
        k_scan3<<<g, 256>>>();
    }

    // 7) out = states @ W_out^T + tokens + b_out + b_skip   [16384 x 1024], K=256
    {
        dim3 g(Dd/128, Mm/128);
        k_gemm<<<g, 256>>>(st, W_out, out, tokens, b_out, b_skip, Mm, Dd, Nn);
    }

    // 8) out += x @ W_skip^T   [16384 x 1024], K=1024
    {
        dim3 g(Dd/128, Mm/128);
        k_gemm<<<g, 256>>>(x, W_skip, out, out, nullptr, nullptr, Mm, Dd, Dd);
    }
}

// round 3
// speedup vs baseline: 1.4791x; 1.4791x over previous
#include <cuda_runtime.h>
#include <math.h>
#include <cstdint>

// Problem dims (fixed for this dataset entry)
#define Bb 4
#define Ss 4096
#define Dd 1024
#define Nn 256
#define Mm (Bb*Ss)            // 16384 tokens
#define CHUNK 64
#define NCHUNK (Ss/CHUNK)     // 64

// Scratch (allocations are forbidden; use device globals)
__device__ float g_x[(size_t)Mm*Dd];        // 64 MB  rmsnormed tokens
__device__ float g_u[(size_t)Mm*Nn];        // 16 MB  input projection
__device__ float g_states[(size_t)Mm*Nn];   // 16 MB  scan states
__device__ float g_loc[Bb*NCHUNK*Nn];       // chunk-local final states
__device__ float g_init[Bb*NCHUNK*Nn];      // chunk initial states
__device__ float g_decay[Nn];
__device__ float g_decayL[Nn];              // decay^CHUNK

// ---------------------------------------------------------------------------
// decay = sigmoid(log_decay); decayL = decay^64 (6 squarings)
__global__ void k_decay(const float* __restrict__ log_decay) {
    int n = threadIdx.x;
    float d = 1.0f / (1.0f + expf(-log_decay[n]));
    g_decay[n] = d;
    float p = d;
    #pragma unroll
    for (int i = 0; i < 6; i++) p *= p;
    g_decayL[n] = p;
}

// ---------------------------------------------------------------------------
// RMSNorm: one block per token, 256 threads, float4
__global__ void __launch_bounds__(256) k_rmsnorm(const float* __restrict__ tokens,
                                                 const float* __restrict__ norm_w) {
    int t = blockIdx.x;
    const float4* tp = (const float4*)(tokens + (size_t)t * Dd);
    float4 v = tp[threadIdx.x];
    float ss = v.x*v.x + v.y*v.y + v.z*v.z + v.w*v.w;
    #pragma unroll
    for (int o = 16; o > 0; o >>= 1) ss += __shfl_xor_sync(0xffffffffu, ss, o);
    __shared__ float wsum[8];
    int wid = threadIdx.x >> 5, lane = threadIdx.x & 31;
    if (lane == 0) wsum[wid] = ss;
    __syncthreads();
    float tot = 0.f;
    #pragma unroll
    for (int i = 0; i < 8; i++) tot += wsum[i];
    float scale = rsqrtf(tot * (1.0f / Dd) + 1e-4f);
    float4 w = ((const float4*)norm_w)[threadIdx.x];
    float4 o;
    o.x = v.x * scale * w.x;
    o.y = v.y * scale * w.y;
    o.z = v.z * scale * w.z;
    o.w = v.w * scale * w.w;
    ((float4*)(g_x + (size_t)t * Dd))[threadIdx.x] = o;
}

// ---------------------------------------------------------------------------
// 3xTF32 tensor-core GEMM.
// C[m,n] = sum_k A[m,k]*Bw[n,k]  (+bias0[n]) (+bias1[n]) (+src[m,n])
// Optionally a second product (A2,B2,K2) accumulated into the same tile
// before the epilogue (used to fuse  states@W_out^T + x@W_skip^T).
//
// CTA: 128x128 tile, 128 threads = 4 warps (2x2), warp tile 64x64.
// BK=16 (two k8 steps). Smem [k][m] pitch 136 -> conflict-free LDS/STS.
// Split: big = v & 0xFFFFE000 (exact tf32), small = v - big (exact fp32).
// acc += Ab*Bs + As*Bb + Ab*Bb   (missing As*Bs ~ 2^-24 relative).

__device__ __forceinline__ void mma_tf32(float* d, const float* a, const float* b) {
    asm volatile(
        "mma.sync.aligned.m16n8k8.row.col.f32.tf32.tf32.f32 "
        "{%0,%1,%2,%3},{%4,%5,%6,%7},{%8,%9},{%0,%1,%2,%3};"
        : "+f"(d[0]), "+f"(d[1]), "+f"(d[2]), "+f"(d[3])
        : "r"(__float_as_uint(a[0])), "r"(__float_as_uint(a[1])),
          "r"(__float_as_uint(a[2])), "r"(__float_as_uint(a[3])),
          "r"(__float_as_uint(b[0])), "r"(__float_as_uint(b[1])));
}

__device__ __forceinline__ void gemm3t_loop(
    const float* __restrict__ A, const float* __restrict__ B, int K,
    int m0, int n0, int tid,
    float (*Abig)[136], float (*Asml)[136],
    float (*Bbig)[136], float (*Bsml)[136],
    float (&acc)[4][8][4])
{
    const int lane = tid & 31;
    const int w = tid >> 5;
    const int g = lane >> 2;          // 0..7
    const int t4 = lane & 3;          // 0..3
    const int wm0 = (w >> 1) * 64;    // warp row offset in tile
    const int wn0 = (w & 1) * 64;     // warp col offset in tile

    const float* Ap = A + (size_t)(m0 + tid) * K;
    const float* Bp = B + (size_t)(n0 + tid) * K;

    float4 pa[4], pb[4];
    #pragma unroll
    for (int i = 0; i < 4; i++) {
        pa[i] = *(const float4*)(Ap + i * 4);
        pb[i] = *(const float4*)(Bp + i * 4);
    }

    for (int k0 = 0; k0 < K; k0 += 16) {
        // split + transpose-store this tile
        #pragma unroll
        for (int i = 0; i < 4; i++) {
            float va[4] = {pa[i].x, pa[i].y, pa[i].z, pa[i].w};
            float vb[4] = {pb[i].x, pb[i].y, pb[i].z, pb[i].w};
            #pragma unroll
            for (int j = 0; j < 4; j++) {
                int k = i * 4 + j;
                float v = va[j];
                float big = __uint_as_float(__float_as_uint(v) & 0xffffe000u);
                Abig[k][tid] = big; Asml[k][tid] = v - big;
                v = vb[j];
                big = __uint_as_float(__float_as_uint(v) & 0xffffe000u);
                Bbig[k][tid] = big; Bsml[k][tid] = v - big;
            }
        }
        __syncthreads();

        // prefetch next tile
        if (k0 + 16 < K) {
            #pragma unroll
            for (int i = 0; i < 4; i++) {
                pa[i] = *(const float4*)(Ap + k0 + 16 + i * 4);
                pb[i] = *(const float4*)(Bp + k0 + 16 + i * 4);
            }
        }

        // two k8 MMA steps
        #pragma unroll
        for (int kk = 0; kk < 16; kk += 8) {
            float bbf[8][2], bsf[8][2];
            #pragma unroll
            for (int nt = 0; nt < 8; nt++) {
                int n = wn0 + nt * 8 + g;
                bbf[nt][0] = Bbig[kk + t4][n];
                bbf[nt][1] = Bbig[kk + t4 + 4][n];
                bsf[nt][0] = Bsml[kk + t4][n];
                bsf[nt][1] = Bsml[kk + t4 + 4][n];
            }
            #pragma unroll
            for (int mt = 0; mt < 4; mt++) {
                int m = wm0 + mt * 16 + g;
                float abf[4] = {Abig[kk + t4][m],     Abig[kk + t4][m + 8],
                                Abig[kk + t4 + 4][m], Abig[kk + t4 + 4][m + 8]};
                float asf[4] = {Asml[kk + t4][m],     Asml[kk + t4][m + 8],
                                Asml[kk + t4 + 4][m], Asml[kk + t4 + 4][m + 8]};
                #pragma unroll
                for (int nt = 0; nt < 8; nt++) {
                    mma_tf32(acc[mt][nt], abf, bsf[nt]);
                    mma_tf32(acc[mt][nt], asf, bbf[nt]);
                    mma_tf32(acc[mt][nt], abf, bbf[nt]);
                }
            }
        }
        __syncthreads();
    }
}

__global__ void __launch_bounds__(128) k_gemm3t(
    const float* __restrict__ A1, const float* __restrict__ B1, int K1,
    const float* __restrict__ A2, const float* __restrict__ B2, int K2,
    float* __restrict__ C, const float* __restrict__ src,
    const float* __restrict__ bias0, const float* __restrict__ bias1,
    int M, int N)
{
    __shared__ float Abig[16][136];
    __shared__ float Asml[16][136];
    __shared__ float Bbig[16][136];
    __shared__ float Bsml[16][136];

    const int tid = threadIdx.x;
    const int m0 = blockIdx.y * 128;
    const int n0 = blockIdx.x * 128;

    float acc[4][8][4];
    #pragma unroll
    for (int mt = 0; mt < 4; mt++)
        #pragma unroll
        for (int nt = 0; nt < 8; nt++)
            #pragma unroll
            for (int r = 0; r < 4; r++) acc[mt][nt][r] = 0.f;

    gemm3t_loop(A1, B1, K1, m0, n0, tid, Abig, Asml, Bbig, Bsml, acc);
    if (A2)
        gemm3t_loop(A2, B2, K2, m0, n0, tid, Abig, Asml, Bbig, Bsml, acc);

    // epilogue
    const int lane = tid & 31;
    const int w = tid >> 5;
    const int g = lane >> 2;
    const int t4 = lane & 3;
    const int wm0 = (w >> 1) * 64;
    const int wn0 = (w & 1) * 64;

    #pragma unroll
    for (int nt = 0; nt < 8; nt++) {
        int c = n0 + wn0 + nt * 8 + 2 * t4;
        float add0 = 0.f, add1 = 0.f;
        if (bias0) { add0 += bias0[c]; add1 += bias0[c + 1]; }
        if (bias1) { add0 += bias1[c]; add1 += bias1[c + 1]; }
        #pragma unroll
        for (int mt = 0; mt < 4; mt++) {
            int r0 = m0 + wm0 + mt * 16 + g;
            int r1 = r0 + 8;
            float2 v0 = make_float2(acc[mt][nt][0] + add0, acc[mt][nt][1] + add1);
            float2 v1 = make_float2(acc[mt][nt][2] + add0, acc[mt][nt][3] + add1);
            size_t o0 = (size_t)r0 * N + c;
            size_t o1 = (size_t)r1 * N + c;
            if (src) {
                float2 s0 = *(const float2*)(src + o0);
                float2 s1 = *(const float2*)(src + o1);
                v0.x += s0.x; v0.y += s0.y;
                v1.x += s1.x; v1.y += s1.y;
            }
            *(float2*)(C + o0) = v0;
            *(float2*)(C + o1) = v1;
        }
    }
}

// ---------------------------------------------------------------------------
// Chunked linear scan: state_t = decay*state_{t-1} + u_t
__global__ void __launch_bounds__(256) k_scan1() {
    int c = blockIdx.x, b = blockIdx.y, n = threadIdx.x;
    float d = g_decay[n];
    const float* up = g_u + ((size_t)(b*Ss + c*CHUNK)) * Nn + n;
    float s = 0.f;
    #pragma unroll 8
    for (int t = 0; t < CHUNK; t++) s = fmaf(d, s, up[(size_t)t * Nn]);
    g_loc[(b*NCHUNK + c)*Nn + n] = s;
}

__global__ void k_scan2() {
    int idx = threadIdx.x + blockIdx.x * blockDim.x;   // <<<4,256>>> -> 1024
    int b = idx >> 8, n = idx & 255;
    float dL = g_decayL[n];
    float init = 0.f;
    for (int c = 0; c < NCHUNK; c++) {
        g_init[(b*NCHUNK + c)*Nn + n] = init;
        init = fmaf(dL, init, g_loc[(b*NCHUNK + c)*Nn + n]);
    }
}

__global__ void __launch_bounds__(256) k_scan3() {
    int c = blockIdx.x, b = blockIdx.y, n = threadIdx.x;
    float d = g_decay[n];
    size_t base = ((size_t)(b*Ss + c*CHUNK)) * Nn + n;
    float s = g_init[(b*NCHUNK + c)*Nn + n];
    #pragma unroll 8
    for (int t = 0; t < CHUNK; t++) {
        s = fmaf(d, s, g_u[base + (size_t)t * Nn]);
        g_states[base + (size_t)t * Nn] = s;
    }
}

// ---------------------------------------------------------------------------
extern "C" void kernel_launch(void* const* d_in, const int* in_sizes, int n_in,
                              void* d_out, int out_size)
{
    const float* tokens    = (const float*)d_in[0];
    const float* norm_w    = (const float*)d_in[1];
    const float* W_in      = (const float*)d_in[2];
    const float* b_in      = (const float*)d_in[3];
    const float* W_out     = (const float*)d_in[4];
    const float* b_out     = (const float*)d_in[5];
    const float* W_skip    = (const float*)d_in[6];
    const float* b_skip    = (const float*)d_in[7];
    const float* log_decay = (const float*)d_in[8];
    float* out = (float*)d_out;

    void *px = nullptr, *pu = nullptr, *ps = nullptr;
    cudaGetSymbolAddress(&px, g_x);
    cudaGetSymbolAddress(&pu, g_u);
    cudaGetSymbolAddress(&ps, g_states);
    float* x  = (float*)px;
    float* u  = (float*)pu;
    float* st = (float*)ps;

    // 1) decay precompute
    k_decay<<<1, Nn>>>(log_decay);

    // 2) RMSNorm -> g_x
    k_rmsnorm<<<Mm, 256>>>(tokens, norm_w);

    // 3) u = x @ W_in^T + b_in   [16384 x 256], K=1024
    {
        dim3 g(Nn/128, Mm/128);
        k_gemm3t<<<g, 128>>>(x, W_in, Dd, nullptr, nullptr, 0,
                             u, nullptr, b_in, nullptr, Mm, Nn);
    }

    // 4-6) chunked scan -> g_states
    {
        dim3 g(NCHUNK, Bb);
        k_scan1<<<g, 256>>>();
        k_scan2<<<4, 256>>>();
        k_scan3<<<g, 256>>>();
    }

    // 7) out = states @ W_out^T + x @ W_skip^T + tokens + b_out + b_skip
    {
        dim3 g(Dd/128, Mm/128);
        k_gemm3t<<<g, 128>>>(st, W_out, Nn, x, W_skip, Dd,
                             out, tokens, b_out, b_skip, Mm, Dd);
    }
}

// round 4
// speedup vs baseline: 2.0465x; 1.3836x over previous
#include <cuda_runtime.h>
#include <cuda_bf16.h>
#include <math.h>
#include <cstdint>

// Problem dims (fixed for this dataset entry)
#define Bb 4
#define Ss 4096
#define Dd 1024
#define Nn 256
#define Mm (Bb*Ss)            // 16384 tokens
#define CHUNK 64
#define NCHUNK (Ss/CHUNK)     // 64

typedef __nv_bfloat16 bf16;
typedef __nv_bfloat162 bf162;

// Scratch (allocations forbidden -> device globals)
__device__ bf16  g_xb0[(size_t)Mm*Dd];      // 32 MB  x split hi
__device__ bf16  g_xb1[(size_t)Mm*Dd];      // 32 MB  x split lo
__device__ bf16  g_tb0[(size_t)Mm*Nn];      // 8 MB   states split hi
__device__ bf16  g_tb1[(size_t)Mm*Nn];      // 8 MB   states split lo
__device__ float g_u[(size_t)Mm*Nn];        // 16 MB  input projection
__device__ bf16  g_wib0[Nn*Dd], g_wib1[Nn*Dd];   // W_in split
__device__ bf16  g_wob0[Dd*Nn], g_wob1[Dd*Nn];   // W_out split
__device__ bf16  g_wsb0[Dd*Dd], g_wsb1[Dd*Dd];   // W_skip split
__device__ float g_loc[Bb*NCHUNK*Nn];
__device__ float g_init[Bb*NCHUNK*Nn];
__device__ float g_decay[Nn];
__device__ float g_decayL[Nn];

// ---------------------------------------------------------------------------
__device__ __forceinline__ void split2(float v, bf16& b0, bf16& b1) {
    b0 = __float2bfloat16_rn(v);
    b1 = __float2bfloat16_rn(v - __bfloat162float(b0));
}

// decay = sigmoid(log_decay); decayL = decay^64
__global__ void k_decay(const float* __restrict__ log_decay) {
    int n = threadIdx.x;
    float d = 1.0f / (1.0f + expf(-log_decay[n]));
    g_decay[n] = d;
    float p = d;
    #pragma unroll
    for (int i = 0; i < 6; i++) p *= p;
    g_decayL[n] = p;
}

// Split a fp32 matrix into bf16 hi/lo arrays
__global__ void k_splitW(const float* __restrict__ src, bf16* __restrict__ d0,
                         bf16* __restrict__ d1, int n) {
    int i = blockIdx.x * blockDim.x + threadIdx.x;
    if (i < n) {
        bf16 b0, b1;
        split2(src[i], b0, b1);
        d0[i] = b0; d1[i] = b1;
    }
}

// ---------------------------------------------------------------------------
// RMSNorm: one block per token, 256 threads, float4; emits bf16 split x
__global__ void __launch_bounds__(256) k_rmsnorm(const float* __restrict__ tokens,
                                                 const float* __restrict__ norm_w) {
    int t = blockIdx.x;
    const float4* tp = (const float4*)(tokens + (size_t)t * Dd);
    float4 v = tp[threadIdx.x];
    float ss = v.x*v.x + v.y*v.y + v.z*v.z + v.w*v.w;
    #pragma unroll
    for (int o = 16; o > 0; o >>= 1) ss += __shfl_xor_sync(0xffffffffu, ss, o);
    __shared__ float wsum[8];
    int wid = threadIdx.x >> 5, lane = threadIdx.x & 31;
    if (lane == 0) wsum[wid] = ss;
    __syncthreads();
    float tot = 0.f;
    #pragma unroll
    for (int i = 0; i < 8; i++) tot += wsum[i];
    float scale = rsqrtf(tot * (1.0f / Dd) + 1e-4f);
    float4 w = ((const float4*)norm_w)[threadIdx.x];
    float o[4];
    o[0] = v.x * scale * w.x;
    o[1] = v.y * scale * w.y;
    o[2] = v.z * scale * w.z;
    o[3] = v.w * scale * w.w;
    bf16 h0[4], h1[4];
    #pragma unroll
    for (int i = 0; i < 4; i++) split2(o[i], h0[i], h1[i]);
    bf162* p0 = (bf162*)(g_xb0 + (size_t)t * Dd);
    bf162* p1 = (bf162*)(g_xb1 + (size_t)t * Dd);
    p0[2*threadIdx.x]   = bf162(h0[0], h0[1]);
    p0[2*threadIdx.x+1] = bf162(h0[2], h0[3]);
    p1[2*threadIdx.x]   = bf162(h1[0], h1[1]);
    p1[2*threadIdx.x+1] = bf162(h1[2], h1[3]);
}

// ---------------------------------------------------------------------------
// 3xBF16 tensor-core GEMM on pre-split operands.
// C[m,n] = sum_k A[m,k]*Bw[n,k] (+bias0[n]) (+bias1[n]) (+src[m,n])
// A = A0+A1, B = B0+B1 (bf16 hi/lo). acc += A0*B1 + A1*B0 + A0*B0.
// CTA: 128x128 tile, 128 threads = 4 warps (2x2), warp tile 64x64.
// BK=16 -> one m16n8k16 per (mt,nt,product). Smem [kw][m] pitch 136,
// word [kw][m] = {Aval[m][2kw], Aval[m][2kw+1]} (bf16x2) -> conflict-free.

__device__ __forceinline__ void mma_bf16(float* d, const uint32_t* a, const uint32_t* b) {
    asm volatile(
        "mma.sync.aligned.m16n8k16.row.col.f32.bf16.bf16.f32 "
        "{%0,%1,%2,%3},{%4,%5,%6,%7},{%8,%9},{%0,%1,%2,%3};"
        : "+f"(d[0]), "+f"(d[1]), "+f"(d[2]), "+f"(d[3])
        : "r"(a[0]), "r"(a[1]), "r"(a[2]), "r"(a[3]),
          "r"(b[0]), "r"(b[1]));
}

__device__ __forceinline__ void gemm_loop(
    const bf16* __restrict__ A0, const bf16* __restrict__ A1,
    const bf16* __restrict__ B0, const bf16* __restrict__ B1, int K,
    int m0, int n0, int tid,
    uint32_t (*sA0)[136], uint32_t (*sA1)[136],
    uint32_t (*sB0)[136], uint32_t (*sB1)[136],
    float (&acc)[4][8][4])
{
    const int lane = tid & 31;
    const int w = tid >> 5;
    const int g = lane >> 2;          // 0..7
    const int t4 = lane & 3;          // 0..3
    const int wm0 = (w >> 1) * 64;
    const int wn0 = (w & 1) * 64;

    const bf16* Ap0 = A0 + (size_t)(m0 + tid) * K;
    const bf16* Ap1 = A1 + (size_t)(m0 + tid) * K;
    const bf16* Bp0 = B0 + (size_t)(n0 + tid) * K;
    const bf16* Bp1 = B1 + (size_t)(n0 + tid) * K;

    uint4 pa0[2], pa1[2], pb0[2], pb1[2];   // 16 bf16 each operand
    #pragma unroll
    for (int i = 0; i < 2; i++) {
        pa0[i] = ((const uint4*)Ap0)[i];
        pa1[i] = ((const uint4*)Ap1)[i];
        pb0[i] = ((const uint4*)Bp0)[i];
        pb1[i] = ((const uint4*)Bp1)[i];
    }

    for (int k0 = 0; k0 < K; k0 += 16) {
        // store tile to smem (word j holds k=2j,2j+1)
        const uint32_t* wa0 = (const uint32_t*)pa0;
        const uint32_t* wa1 = (const uint32_t*)pa1;
        const uint32_t* wb0 = (const uint32_t*)pb0;
        const uint32_t* wb1 = (const uint32_t*)pb1;
        #pragma unroll
        for (int j = 0; j < 8; j++) {
            sA0[j][tid] = wa0[j];
            sA1[j][tid] = wa1[j];
            sB0[j][tid] = wb0[j];
            sB1[j][tid] = wb1[j];
        }
        __syncthreads();

        // prefetch next tile
        if (k0 + 16 < K) {
            const uint4* qa0 = (const uint4*)(Ap0 + k0 + 16);
            const uint4* qa1 = (const uint4*)(Ap1 + k0 + 16);
            const uint4* qb0 = (const uint4*)(Bp0 + k0 + 16);
            const uint4* qb1 = (const uint4*)(Bp1 + k0 + 16);
            #pragma unroll
            for (int i = 0; i < 2; i++) {
                pa0[i] = qa0[i]; pa1[i] = qa1[i];
                pb0[i] = qb0[i]; pb1[i] = qb1[i];
            }
        }

        // fragments + MMAs
        uint32_t b0f[8][2], b1f[8][2];
        #pragma unroll
        for (int nt = 0; nt < 8; nt++) {
            int n = wn0 + nt * 8 + g;
            b0f[nt][0] = sB0[t4][n];     b0f[nt][1] = sB0[t4 + 4][n];
            b1f[nt][0] = sB1[t4][n];     b1f[nt][1] = sB1[t4 + 4][n];
        }
        #pragma unroll
        for (int mt = 0; mt < 4; mt++) {
            int m = wm0 + mt * 16 + g;
            uint32_t a0f[4] = {sA0[t4][m], sA0[t4][m + 8],
                               sA0[t4 + 4][m], sA0[t4 + 4][m + 8]};
            uint32_t a1f[4] = {sA1[t4][m], sA1[t4][m + 8],
                               sA1[t4 + 4][m], sA1[t4 + 4][m + 8]};
            #pragma unroll
            for (int nt = 0; nt < 8; nt++) {
                mma_bf16(acc[mt][nt], a0f, b1f[nt]);
                mma_bf16(acc[mt][nt], a1f, b0f[nt]);
                mma_bf16(acc[mt][nt], a0f, b0f[nt]);
            }
        }
        __syncthreads();
    }
}

__global__ void __launch_bounds__(128) k_gemmbf(
    const bf16* __restrict__ A10, const bf16* __restrict__ A11,
    const bf16* __restrict__ B10, const bf16* __restrict__ B11, int K1,
    const bf16* __restrict__ A20, const bf16* __restrict__ A21,
    const bf16* __restrict__ B20, const bf16* __restrict__ B21, int K2,
    float* __restrict__ C, const float* __restrict__ src,
    const float* __restrict__ bias0, const float* __restrict__ bias1,
    int M, int N)
{
    __shared__ uint32_t sA0[8][136];
    __shared__ uint32_t sA1[8][136];
    __shared__ uint32_t sB0[8][136];
    __shared__ uint32_t sB1[8][136];

    const int tid = threadIdx.x;
    const int m0 = blockIdx.y * 128;
    const int n0 = blockIdx.x * 128;

    float acc[4][8][4];
    #pragma unroll
    for (int mt = 0; mt < 4; mt++)
        #pragma unroll
        for (int nt = 0; nt < 8; nt++)
            #pragma unroll
            for (int r = 0; r < 4; r++) acc[mt][nt][r] = 0.f;

    gemm_loop(A10, A11, B10, B11, K1, m0, n0, tid, sA0, sA1, sB0, sB1, acc);
    if (A20)
        gemm_loop(A20, A21, B20, B21, K2, m0, n0, tid, sA0, sA1, sB0, sB1, acc);

    // epilogue
    const int lane = tid & 31;
    const int w = tid >> 5;
    const int g = lane >> 2;
    const int t4 = lane & 3;
    const int wm0 = (w >> 1) * 64;
    const int wn0 = (w & 1) * 64;

    #pragma unroll
    for (int nt = 0; nt < 8; nt++) {
        int c = n0 + wn0 + nt * 8 + 2 * t4;
        float add0 = 0.f, add1 = 0.f;
        if (bias0) { add0 += bias0[c]; add1 += bias0[c + 1]; }
        if (bias1) { add0 += bias1[c]; add1 += bias1[c + 1]; }
        #pragma unroll
        for (int mt = 0; mt < 4; mt++) {
            int r0 = m0 + wm0 + mt * 16 + g;
            int r1 = r0 + 8;
            float2 v0 = make_float2(acc[mt][nt][0] + add0, acc[mt][nt][1] + add1);
            float2 v1 = make_float2(acc[mt][nt][2] + add0, acc[mt][nt][3] + add1);
            size_t o0 = (size_t)r0 * N + c;
            size_t o1 = (size_t)r1 * N + c;
            if (src) {
                float2 s0 = *(const float2*)(src + o0);
                float2 s1 = *(const float2*)(src + o1);
                v0.x += s0.x; v0.y += s0.y;
                v1.x += s1.x; v1.y += s1.y;
            }
            *(float2*)(C + o0) = v0;
            *(float2*)(C + o1) = v1;
        }
    }
}

// ---------------------------------------------------------------------------
// Chunked linear scan: state_t = decay*state_{t-1} + u_t
__global__ void __launch_bounds__(256) k_scan1() {
    int c = blockIdx.x, b = blockIdx.y, n = threadIdx.x;
    float d = g_decay[n];
    const float* up = g_u + ((size_t)(b*Ss + c*CHUNK)) * Nn + n;
    float s = 0.f;
    #pragma unroll 8
    for (int t = 0; t < CHUNK; t++) s = fmaf(d, s, up[(size_t)t * Nn]);
    g_loc[(b*NCHUNK + c)*Nn + n] = s;
}

__global__ void k_scan2() {
    int idx = threadIdx.x + blockIdx.x * blockDim.x;   // <<<4,256>>> -> 1024
    int b = idx >> 8, n = idx & 255;
    float dL = g_decayL[n];
    float init = 0.f;
    for (int c = 0; c < NCHUNK; c++) {
        g_init[(b*NCHUNK + c)*Nn + n] = init;
        init = fmaf(dL, init, g_loc[(b*NCHUNK + c)*Nn + n]);
    }
}

// Pass 3: rescan with correct init, write bf16-split states
__global__ void __launch_bounds__(256) k_scan3() {
    int c = blockIdx.x, b = blockIdx.y, n = threadIdx.x;
    float d = g_decay[n];
    size_t base = ((size_t)(b*Ss + c*CHUNK)) * Nn + n;
    float s = g_init[(b*NCHUNK + c)*Nn + n];
    #pragma unroll 4
    for (int t = 0; t < CHUNK; t++) {
        s = fmaf(d, s, g_u[base + (size_t)t * Nn]);
        bf16 b0, b1;
        split2(s, b0, b1);
        g_tb0[base + (size_t)t * Nn] = b0;
        g_tb1[base + (size_t)t * Nn] = b1;
    }
}

// ---------------------------------------------------------------------------
extern "C" void kernel_launch(void* const* d_in, const int* in_sizes, int n_in,
                              void* d_out, int out_size)
{
    const float* tokens    = (const float*)d_in[0];
    const float* norm_w    = (const float*)d_in[1];
    const float* W_in      = (const float*)d_in[2];
    const float* b_in      = (const float*)d_in[3];
    const float* W_out     = (const float*)d_in[4];
    const float* b_out     = (const float*)d_in[5];
    const float* W_skip    = (const float*)d_in[6];
    const float* b_skip    = (const float*)d_in[7];
    const float* log_decay = (const float*)d_in[8];
    float* out = (float*)d_out;

    void *p;
    cudaGetSymbolAddress(&p, g_xb0);  bf16* xb0 = (bf16*)p;
    cudaGetSymbolAddress(&p, g_xb1);  bf16* xb1 = (bf16*)p;
    cudaGetSymbolAddress(&p, g_tb0);  bf16* tb0 = (bf16*)p;
    cudaGetSymbolAddress(&p, g_tb1);  bf16* tb1 = (bf16*)p;
    cudaGetSymbolAddress(&p, g_u);    float* u  = (float*)p;
    cudaGetSymbolAddress(&p, g_wib0); bf16* wib0 = (bf16*)p;
    cudaGetSymbolAddress(&p, g_wib1); bf16* wib1 = (bf16*)p;
    cudaGetSymbolAddress(&p, g_wob0); bf16* wob0 = (bf16*)p;
    cudaGetSymbolAddress(&p, g_wob1); bf16* wob1 = (bf16*)p;
    cudaGetSymbolAddress(&p, g_wsb0); bf16* wsb0 = (bf16*)p;
    cudaGetSymbolAddress(&p, g_wsb1); bf16* wsb1 = (bf16*)p;

    // 1) decay precompute + weight splits
    k_decay<<<1, Nn>>>(log_decay);
    k_splitW<<<(Nn*Dd + 255)/256, 256>>>(W_in,  wib0, wib1, Nn*Dd);
    k_splitW<<<(Dd*Nn + 255)/256, 256>>>(W_out, wob0, wob1, Dd*Nn);
    k_splitW<<<(Dd*Dd + 255)/256, 256>>>(W_skip, wsb0, wsb1, Dd*Dd);

    // 2) RMSNorm -> split x
    k_rmsnorm<<<Mm, 256>>>(tokens, norm_w);

    // 3) u = x @ W_in^T + b_in   [16384 x 256], K=1024
    {
        dim3 g(Nn/128, Mm/128);
        k_gemmbf<<<g, 128>>>(xb0, xb1, wib0, wib1, Dd,
                             nullptr, nullptr, nullptr, nullptr, 0,
                             u, nullptr, b_in, nullptr, Mm, Nn);
    }

    // 4-6) chunked scan -> split states
    {
        dim3 g(NCHUNK, Bb);
        k_scan1<<<g, 256>>>();
        k_scan2<<<4, 256>>>();
        k_scan3<<<g, 256>>>();
    }

    // 7) out = states @ W_out^T + x @ W_skip^T + tokens + b_out + b_skip
    {
        dim3 g(Dd/128, Mm/128);
        k_gemmbf<<<g, 128>>>(tb0, tb1, wob0, wob1, Nn,
                             xb0, xb1, wsb0, wsb1, Dd,
                             out, tokens, b_out, b_skip, Mm, Dd);
    }
}

// round 6
// speedup vs baseline: 2.5225x; 1.2326x over previous
#include <cuda_runtime.h>
#include <cuda_fp16.h>
#include <math.h>
#include <cstdint>

// Problem dims (fixed for this dataset entry)
#define Bb 4
#define Ss 4096
#define Dd 1024
#define Nn 256
#define Mm (Bb*Ss)            // 16384 tokens
#define CHUNK 64
#define NCHUNK (Ss/CHUNK)     // 64

// Scratch (allocations forbidden -> device globals)
__device__ __half g_xh[(size_t)Mm*Dd];      // 32 MB  x (fp16)
__device__ __half g_th[(size_t)Mm*Nn];      // 8 MB   states (fp16)
__device__ float  g_u[(size_t)Mm*Nn];       // 16 MB  input projection
__device__ __half g_wi0[Nn*Dd], g_wi1[Nn*Dd];   // W_in hi/lo
__device__ __half g_wo0[Dd*Nn], g_wo1[Dd*Nn];   // W_out hi/lo
__device__ __half g_ws0[Dd*Dd], g_ws1[Dd*Dd];   // W_skip hi/lo
__device__ float  g_loc[Bb*NCHUNK*Nn];
__device__ float  g_init[Bb*NCHUNK*Nn];
__device__ float  g_decay[Nn];
__device__ float  g_decayL[Nn];

// ---------------------------------------------------------------------------
__device__ __forceinline__ void splitw(float v, __half& h0, __half& h1) {
    h0 = __float2half_rn(v);
    h1 = __float2half_rn(v - __half2float(h0));
}

__global__ void k_decay(const float* __restrict__ log_decay) {
    int n = threadIdx.x;
    float d = 1.0f / (1.0f + expf(-log_decay[n]));
    g_decay[n] = d;
    float p = d;
    #pragma unroll
    for (int i = 0; i < 6; i++) p *= p;
    g_decayL[n] = p;
}

// Split a fp32 weight matrix into fp16 hi/lo arrays
__global__ void k_splitW(const float* __restrict__ src, __half* __restrict__ d0,
                         __half* __restrict__ d1, int n) {
    int i = blockIdx.x * blockDim.x + threadIdx.x;
    if (i < n) {
        __half h0, h1;
        splitw(src[i], h0, h1);
        d0[i] = h0; d1[i] = h1;
    }
}

// ---------------------------------------------------------------------------
// RMSNorm: one block per token, 256 threads; emits single fp16 x
__global__ void __launch_bounds__(256) k_rmsnorm(const float* __restrict__ tokens,
                                                 const float* __restrict__ norm_w) {
    int t = blockIdx.x;
    const float4* tp = (const float4*)(tokens + (size_t)t * Dd);
    float4 v = tp[threadIdx.x];
    float ss = v.x*v.x + v.y*v.y + v.z*v.z + v.w*v.w;
    #pragma unroll
    for (int o = 16; o > 0; o >>= 1) ss += __shfl_xor_sync(0xffffffffu, ss, o);
    __shared__ float wsum[8];
    int wid = threadIdx.x >> 5, lane = threadIdx.x & 31;
    if (lane == 0) wsum[wid] = ss;
    __syncthreads();
    float tot = 0.f;
    #pragma unroll
    for (int i = 0; i < 8; i++) tot += wsum[i];
    float scale = rsqrtf(tot * (1.0f / Dd) + 1e-4f);
    float4 w = ((const float4*)norm_w)[threadIdx.x];
    __half2* ph = (__half2*)(g_xh + (size_t)t * Dd);
    ph[2*threadIdx.x]   = __floats2half2_rn(v.x * scale * w.x, v.y * scale * w.y);
    ph[2*threadIdx.x+1] = __floats2half2_rn(v.z * scale * w.z, v.w * scale * w.w);
}

// ---------------------------------------------------------------------------
// 2-product fp16 tensor-core GEMM on pre-split weights.
// C[m,n] = sum_k A[m,k]*(B0[n,k]+B1[n,k]) (+bias0[n]) (+bias1[n]) (+src[m,n])
// A fp16 (activations), B0/B1 fp16 hi/lo (weights).
// CTA: 128x128 tile, 128 threads = 4 warps (2x2), warp tile 64x64.
// BK=16 -> m16n8k16. Smem [kw][m] pitch 136, word = 2 consecutive k halves.

__device__ __forceinline__ void mma_f16(float* d, const uint32_t* a, const uint32_t* b) {
    asm volatile(
        "mma.sync.aligned.m16n8k16.row.col.f32.f16.f16.f32 "
        "{%0,%1,%2,%3},{%4,%5,%6,%7},{%8,%9},{%0,%1,%2,%3};"
        : "+f"(d[0]), "+f"(d[1]), "+f"(d[2]), "+f"(d[3])
        : "r"(a[0]), "r"(a[1]), "r"(a[2]), "r"(a[3]),
          "r"(b[0]), "r"(b[1]));
}

__device__ __forceinline__ void gemm_loop(
    const __half* __restrict__ A,
    const __half* __restrict__ B0, const __half* __restrict__ B1, int K,
    int m0, int n0, int tid,
    uint32_t (*sA)[136], uint32_t (*sB0)[136], uint32_t (*sB1)[136],
    float (&acc)[4][8][4])
{
    const int lane = tid & 31;
    const int w = tid >> 5;
    const int g = lane >> 2;          // 0..7
    const int t4 = lane & 3;          // 0..3
    const int wm0 = (w >> 1) * 64;
    const int wn0 = (w & 1) * 64;

    const __half* Ap  = A  + (size_t)(m0 + tid) * K;
    const __half* Bp0 = B0 + (size_t)(n0 + tid) * K;
    const __half* Bp1 = B1 + (size_t)(n0 + tid) * K;

    uint4 pa[2], pb0[2], pb1[2];   // 16 halves each operand
    #pragma unroll
    for (int i = 0; i < 2; i++) {
        pa[i]  = ((const uint4*)Ap)[i];
        pb0[i] = ((const uint4*)Bp0)[i];
        pb1[i] = ((const uint4*)Bp1)[i];
    }

    for (int k0 = 0; k0 < K; k0 += 16) {
        const uint32_t* wa  = (const uint32_t*)pa;
        const uint32_t* wb0 = (const uint32_t*)pb0;
        const uint32_t* wb1 = (const uint32_t*)pb1;
        #pragma unroll
        for (int j = 0; j < 8; j++) {
            sA[j][tid]  = wa[j];
            sB0[j][tid] = wb0[j];
            sB1[j][tid] = wb1[j];
        }
        __syncthreads();

        // prefetch next tile
        if (k0 + 16 < K) {
            const uint4* qa  = (const uint4*)(Ap  + k0 + 16);
            const uint4* qb0 = (const uint4*)(Bp0 + k0 + 16);
            const uint4* qb1 = (const uint4*)(Bp1 + k0 + 16);
            #pragma unroll
            for (int i = 0; i < 2; i++) {
                pa[i] = qa[i]; pb0[i] = qb0[i]; pb1[i] = qb1[i];
            }
        }

        // fragments + MMAs
        uint32_t b0f[8][2], b1f[8][2];
        #pragma unroll
        for (int nt = 0; nt < 8; nt++) {
            int n = wn0 + nt * 8 + g;
            b0f[nt][0] = sB0[t4][n];     b0f[nt][1] = sB0[t4 + 4][n];
            b1f[nt][0] = sB1[t4][n];     b1f[nt][1] = sB1[t4 + 4][n];
        }
        #pragma unroll
        for (int mt = 0; mt < 4; mt++) {
            int m = wm0 + mt * 16 + g;
            uint32_t af[4] = {sA[t4][m], sA[t4][m + 8],
                              sA[t4 + 4][m], sA[t4 + 4][m + 8]};
            #pragma unroll
            for (int nt = 0; nt < 8; nt++) {
                mma_f16(acc[mt][nt], af, b1f[nt]);
                mma_f16(acc[mt][nt], af, b0f[nt]);
            }
        }
        __syncthreads();
    }
}

__global__ void __launch_bounds__(128) k_gemmh(
    const __half* __restrict__ A1,
    const __half* __restrict__ B10, const __half* __restrict__ B11, int K1,
    const __half* __restrict__ A2,
    const __half* __restrict__ B20, const __half* __restrict__ B21, int K2,
    float* __restrict__ C, const float* __restrict__ src,
    const float* __restrict__ bias0, const float* __restrict__ bias1,
    int M, int N)
{
    __shared__ uint32_t sA[8][136];
    __shared__ uint32_t sB0[8][136];
    __shared__ uint32_t sB1[8][136];

    const int tid = threadIdx.x;
    const int m0 = blockIdx.y * 128;
    const int n0 = blockIdx.x * 128;

    float acc[4][8][4];
    #pragma unroll
    for (int mt = 0; mt < 4; mt++)
        #pragma unroll
        for (int nt = 0; nt < 8; nt++)
            #pragma unroll
            for (int r = 0; r < 4; r++) acc[mt][nt][r] = 0.f;

    gemm_loop(A1, B10, B11, K1, m0, n0, tid, sA, sB0, sB1, acc);
    if (A2)
        gemm_loop(A2, B20, B21, K2, m0, n0, tid, sA, sB0, sB1, acc);

    // epilogue
    const int lane = tid & 31;
    const int w = tid >> 5;
    const int g = lane >> 2;
    const int t4 = lane & 3;
    const int wm0 = (w >> 1) * 64;
    const int wn0 = (w & 1) * 64;

    #pragma unroll
    for (int nt = 0; nt < 8; nt++) {
        int c = n0 + wn0 + nt * 8 + 2 * t4;
        float add0 = 0.f, add1 = 0.f;
        if (bias0) { add0 += bias0[c]; add1 += bias0[c + 1]; }
        if (bias1) { add0 += bias1[c]; add1 += bias1[c + 1]; }
        #pragma unroll
        for (int mt = 0; mt < 4; mt++) {
            int r0 = m0 + wm0 + mt * 16 + g;
            int r1 = r0 + 8;
            float2 v0 = make_float2(acc[mt][nt][0] + add0, acc[mt][nt][1] + add1);
            float2 v1 = make_float2(acc[mt][nt][2] + add0, acc[mt][nt][3] + add1);
            size_t o0 = (size_t)r0 * N + c;
            size_t o1 = (size_t)r1 * N + c;
            if (src) {
                float2 s0 = *(const float2*)(src + o0);
                float2 s1 = *(const float2*)(src + o1);
                v0.x += s0.x; v0.y += s0.y;
                v1.x += s1.x; v1.y += s1.y;
            }
            *(float2*)(C + o0) = v0;
            *(float2*)(C + o1) = v1;
        }
    }
}

// ---------------------------------------------------------------------------
// Chunked linear scan: state_t = decay*state_{t-1} + u_t
__global__ void __launch_bounds__(256) k_scan1() {
    int c = blockIdx.x, b = blockIdx.y, n = threadIdx.x;
    float d = g_decay[n];
    const float* up = g_u + ((size_t)(b*Ss + c*CHUNK)) * Nn + n;
    float s = 0.f;
    #pragma unroll 8
    for (int t = 0; t < CHUNK; t++) s = fmaf(d, s, up[(size_t)t * Nn]);
    g_loc[(b*NCHUNK + c)*Nn + n] = s;
}

__global__ void k_scan2() {
    int idx = threadIdx.x + blockIdx.x * blockDim.x;   // <<<4,256>>> -> 1024
    int b = idx >> 8, n = idx & 255;
    float dL = g_decayL[n];
    float init = 0.f;
    for (int c = 0; c < NCHUNK; c++) {
        g_init[(b*NCHUNK + c)*Nn + n] = init;
        init = fmaf(dL, init, g_loc[(b*NCHUNK + c)*Nn + n]);
    }
}

// Pass 3: rescan with correct init, write fp16 states
__global__ void __launch_bounds__(256) k_scan3() {
    int c = blockIdx.x, b = blockIdx.y, n = threadIdx.x;
    float d = g_decay[n];
    size_t base = ((size_t)(b*Ss + c*CHUNK)) * Nn + n;
    float s = g_init[(b*NCHUNK + c)*Nn + n];
    #pragma unroll 4
    for (int t = 0; t < CHUNK; t++) {
        s = fmaf(d, s, g_u[base + (size_t)t * Nn]);
        g_th[base + (size_t)t * Nn] = __float2half_rn(s);
    }
}

// ---------------------------------------------------------------------------
extern "C" void kernel_launch(void* const* d_in, const int* in_sizes, int n_in,
                              void* d_out, int out_size)
{
    const float* tokens    = (const float*)d_in[0];
    const float* norm_w    = (const float*)d_in[1];
    const float* W_in      = (const float*)d_in[2];
    const float* b_in      = (const float*)d_in[3];
    const float* W_out     = (const float*)d_in[4];
    const float* b_out     = (const float*)d_in[5];
    const float* W_skip    = (const float*)d_in[6];
    const float* b_skip    = (const float*)d_in[7];
    const float* log_decay = (const float*)d_in[8];
    float* out = (float*)d_out;

    void *p;
    cudaGetSymbolAddress(&p, g_xh);  __half* xh = (__half*)p;
    cudaGetSymbolAddress(&p, g_th);  __half* th = (__half*)p;
    cudaGetSymbolAddress(&p, g_u);   float*  u  = (float*)p;
    cudaGetSymbolAddress(&p, g_wi0); __half* wi0 = (__half*)p;
    cudaGetSymbolAddress(&p, g_wi1); __half* wi1 = (__half*)p;
    cudaGetSymbolAddress(&p, g_wo0); __half* wo0 = (__half*)p;
    cudaGetSymbolAddress(&p, g_wo1); __half* wo1 = (__half*)p;
    cudaGetSymbolAddress(&p, g_ws0); __half* ws0 = (__half*)p;
    cudaGetSymbolAddress(&p, g_ws1); __half* ws1 = (__half*)p;

    // 1) decay precompute + weight splits
    k_decay<<<1, Nn>>>(log_decay);
    k_splitW<<<(Nn*Dd + 255)/256, 256>>>(W_in,   wi0, wi1, Nn*Dd);
    k_splitW<<<(Dd*Nn + 255)/256, 256>>>(W_out,  wo0, wo1, Dd*Nn);
    k_splitW<<<(Dd*Dd + 255)/256, 256>>>(W_skip, ws0, ws1, Dd*Dd);

    // 2) RMSNorm -> fp16 x
    k_rmsnorm<<<Mm, 256>>>(tokens, norm_w);

    // 3) u = x @ W_in^T + b_in   [16384 x 256], K=1024
    {
        dim3 g(Nn/128, Mm/128);
        k_gemmh<<<g, 128>>>(xh, wi0, wi1, Dd,
                            nullptr, nullptr, nullptr, 0,
                            u, nullptr, b_in, nullptr, Mm, Nn);
    }

    // 4-6) chunked scan -> fp16 states
    {
        dim3 g(NCHUNK, Bb);
        k_scan1<<<g, 256>>>();
        k_scan2<<<4, 256>>>();
        k_scan3<<<g, 256>>>();
    }

    // 7) out = states @ W_out^T + x @ W_skip^T + tokens + b_out + b_skip
    {
        dim3 g(Dd/128, Mm/128);
        k_gemmh<<<g, 128>>>(th, wo0, wo1, Nn,
                            xh, ws0, ws1, Dd,
                            out, tokens, b_out, b_skip, Mm, Dd);
    }
}

// round 8
// speedup vs baseline: 2.9760x; 1.1798x over previous
#include <cuda_runtime.h>
#include <cuda_fp16.h>
#include <math.h>
#include <cstdint>

// Problem dims (fixed for this dataset entry)
#define Bb 4
#define Ss 4096
#define Dd 1024
#define Nn 256
#define Mm (Bb*Ss)            // 16384 tokens
#define CHUNK 64
#define NCHUNK (Ss/CHUNK)     // 64

// Scratch (allocations forbidden -> device globals)
__device__ __half g_xh[(size_t)Mm*Dd];      // 32 MB  x (fp16)
__device__ __half g_th[(size_t)Mm*Nn];      // 8 MB   states (fp16)
__device__ float  g_u[(size_t)Mm*Nn];       // 16 MB  input projection
__device__ __half g_wi0[Nn*Dd], g_wi1[Nn*Dd];   // W_in hi/lo
__device__ __half g_wo0[Dd*Nn], g_wo1[Dd*Nn];   // W_out hi/lo
__device__ __half g_ws0[Dd*Dd];                  // W_skip (single fp16)
__device__ float  g_loc[Bb*NCHUNK*Nn];
__device__ float  g_init[Bb*NCHUNK*Nn];
__device__ float  g_decay[Nn];
__device__ float  g_decayL[Nn];

// ---------------------------------------------------------------------------
__device__ __forceinline__ void splitw(float v, __half& h0, __half& h1) {
    h0 = __float2half_rn(v);
    h1 = __float2half_rn(v - __half2float(h0));
}

__global__ void k_decay(const float* __restrict__ log_decay) {
    int n = threadIdx.x;
    float d = 1.0f / (1.0f + expf(-log_decay[n]));
    g_decay[n] = d;
    float p = d;
    #pragma unroll
    for (int i = 0; i < 6; i++) p *= p;
    g_decayL[n] = p;
}

// Split a fp32 weight matrix into fp16 hi/lo arrays
__global__ void k_splitW(const float* __restrict__ src, __half* __restrict__ d0,
                         __half* __restrict__ d1, int n) {
    int i = blockIdx.x * blockDim.x + threadIdx.x;
    if (i < n) {
        __half h0, h1;
        splitw(src[i], h0, h1);
        d0[i] = h0; d1[i] = h1;
    }
}

// Convert fp32 -> single fp16
__global__ void k_cvtW(const float* __restrict__ src, __half* __restrict__ d0, int n) {
    int i = blockIdx.x * blockDim.x + threadIdx.x;
    if (i < n) d0[i] = __float2half_rn(src[i]);
}

// ---------------------------------------------------------------------------
// RMSNorm: one block per token, 256 threads; emits single fp16 x
__global__ void __launch_bounds__(256) k_rmsnorm(const float* __restrict__ tokens,
                                                 const float* __restrict__ norm_w) {
    int t = blockIdx.x;
    const float4* tp = (const float4*)(tokens + (size_t)t * Dd);
    float4 v = tp[threadIdx.x];
    float ss = v.x*v.x + v.y*v.y + v.z*v.z + v.w*v.w;
    #pragma unroll
    for (int o = 16; o > 0; o >>= 1) ss += __shfl_xor_sync(0xffffffffu, ss, o);
    __shared__ float wsum[8];
    int wid = threadIdx.x >> 5, lane = threadIdx.x & 31;
    if (lane == 0) wsum[wid] = ss;
    __syncthreads();
    float tot = 0.f;
    #pragma unroll
    for (int i = 0; i < 8; i++) tot += wsum[i];
    float scale = rsqrtf(tot * (1.0f / Dd) + 1e-4f);
    float4 w = ((const float4*)norm_w)[threadIdx.x];
    __half2* ph = (__half2*)(g_xh + (size_t)t * Dd);
    ph[2*threadIdx.x]   = __floats2half2_rn(v.x * scale * w.x, v.y * scale * w.y);
    ph[2*threadIdx.x+1] = __floats2half2_rn(v.z * scale * w.z, v.w * scale * w.w);
}

// ---------------------------------------------------------------------------
// fp16 tensor-core GEMM, 2-product (split weights) and 1-product loops.
// C[m,n] = sum_k A[m,k]*B[n,k] (+bias0[n]) (+bias1[n]) (+src[m,n])
// CTA: 128x128 tile, 128 threads = 4 warps (2x2), warp tile 64x64.
// BK=16 -> m16n8k16. Smem [kw][m] pitch 136.

__device__ __forceinline__ void mma_f16(float* d, const uint32_t* a, const uint32_t* b) {
    asm volatile(
        "mma.sync.aligned.m16n8k16.row.col.f32.f16.f16.f32 "
        "{%0,%1,%2,%3},{%4,%5,%6,%7},{%8,%9},{%0,%1,%2,%3};"
        : "+f"(d[0]), "+f"(d[1]), "+f"(d[2]), "+f"(d[3])
        : "r"(a[0]), "r"(a[1]), "r"(a[2]), "r"(a[3]),
          "r"(b[0]), "r"(b[1]));
}

// 2-product: A * (B0 + B1)
__device__ __forceinline__ void gemm_loop2(
    const __half* __restrict__ A,
    const __half* __restrict__ B0, const __half* __restrict__ B1, int K,
    int m0, int n0, int tid,
    uint32_t (*sA)[136], uint32_t (*sB0)[136], uint32_t (*sB1)[136],
    float (&acc)[4][8][4])
{
    const int lane = tid & 31;
    const int w = tid >> 5;
    const int g = lane >> 2;
    const int t4 = lane & 3;
    const int wm0 = (w >> 1) * 64;
    const int wn0 = (w & 1) * 64;

    const __half* Ap  = A  + (size_t)(m0 + tid) * K;
    const __half* Bp0 = B0 + (size_t)(n0 + tid) * K;
    const __half* Bp1 = B1 + (size_t)(n0 + tid) * K;

    uint4 pa[2], pb0[2], pb1[2];
    #pragma unroll
    for (int i = 0; i < 2; i++) {
        pa[i]  = ((const uint4*)Ap)[i];
        pb0[i] = ((const uint4*)Bp0)[i];
        pb1[i] = ((const uint4*)Bp1)[i];
    }

    for (int k0 = 0; k0 < K; k0 += 16) {
        const uint32_t* wa  = (const uint32_t*)pa;
        const uint32_t* wb0 = (const uint32_t*)pb0;
        const uint32_t* wb1 = (const uint32_t*)pb1;
        #pragma unroll
        for (int j = 0; j < 8; j++) {
            sA[j][tid]  = wa[j];
            sB0[j][tid] = wb0[j];
            sB1[j][tid] = wb1[j];
        }
        __syncthreads();

        if (k0 + 16 < K) {
            const uint4* qa  = (const uint4*)(Ap  + k0 + 16);
            const uint4* qb0 = (const uint4*)(Bp0 + k0 + 16);
            const uint4* qb1 = (const uint4*)(Bp1 + k0 + 16);
            #pragma unroll
            for (int i = 0; i < 2; i++) {
                pa[i] = qa[i]; pb0[i] = qb0[i]; pb1[i] = qb1[i];
            }
        }

        uint32_t b0f[8][2], b1f[8][2];
        #pragma unroll
        for (int nt = 0; nt < 8; nt++) {
            int n = wn0 + nt * 8 + g;
            b0f[nt][0] = sB0[t4][n];     b0f[nt][1] = sB0[t4 + 4][n];
            b1f[nt][0] = sB1[t4][n];     b1f[nt][1] = sB1[t4 + 4][n];
        }
        #pragma unroll
        for (int mt = 0; mt < 4; mt++) {
            int m = wm0 + mt * 16 + g;
            uint32_t af[4] = {sA[t4][m], sA[t4][m + 8],
                              sA[t4 + 4][m], sA[t4 + 4][m + 8]};
            #pragma unroll
            for (int nt = 0; nt < 8; nt++) {
                mma_f16(acc[mt][nt], af, b1f[nt]);
                mma_f16(acc[mt][nt], af, b0f[nt]);
            }
        }
        __syncthreads();
    }
}

// 1-product: A * B0
__device__ __forceinline__ void gemm_loop1(
    const __half* __restrict__ A,
    const __half* __restrict__ B0, int K,
    int m0, int n0, int tid,
    uint32_t (*sA)[136], uint32_t (*sB0)[136],
    float (&acc)[4][8][4])
{
    const int lane = tid & 31;
    const int w = tid >> 5;
    const int g = lane >> 2;
    const int t4 = lane & 3;
    const int wm0 = (w >> 1) * 64;
    const int wn0 = (w & 1) * 64;

    const __half* Ap  = A  + (size_t)(m0 + tid) * K;
    const __half* Bp0 = B0 + (size_t)(n0 + tid) * K;

    uint4 pa[2], pb0[2];
    #pragma unroll
    for (int i = 0; i < 2; i++) {
        pa[i]  = ((const uint4*)Ap)[i];
        pb0[i] = ((const uint4*)Bp0)[i];
    }

    for (int k0 = 0; k0 < K; k0 += 16) {
        const uint32_t* wa  = (const uint32_t*)pa;
        const uint32_t* wb0 = (const uint32_t*)pb0;
        #pragma unroll
        for (int j = 0; j < 8; j++) {
            sA[j][tid]  = wa[j];
            sB0[j][tid] = wb0[j];
        }
        __syncthreads();

        if (k0 + 16 < K) {
            const uint4* qa  = (const uint4*)(Ap  + k0 + 16);
            const uint4* qb0 = (const uint4*)(Bp0 + k0 + 16);
            #pragma unroll
            for (int i = 0; i < 2; i++) {
                pa[i] = qa[i]; pb0[i] = qb0[i];
            }
        }

        uint32_t b0f[8][2];
        #pragma unroll
        for (int nt = 0; nt < 8; nt++) {
            int n = wn0 + nt * 8 + g;
            b0f[nt][0] = sB0[t4][n];     b0f[nt][1] = sB0[t4 + 4][n];
        }
        #pragma unroll
        for (int mt = 0; mt < 4; mt++) {
            int m = wm0 + mt * 16 + g;
            uint32_t af[4] = {sA[t4][m], sA[t4][m + 8],
                              sA[t4 + 4][m], sA[t4 + 4][m + 8]};
            #pragma unroll
            for (int nt = 0; nt < 8; nt++)
                mma_f16(acc[mt][nt], af, b0f[nt]);
        }
        __syncthreads();
    }
}

__global__ void __launch_bounds__(128) k_gemmh(
    const __half* __restrict__ A1,
    const __half* __restrict__ B10, const __half* __restrict__ B11, int K1,
    const __half* __restrict__ A2,
    const __half* __restrict__ B20, int K2,   // second product pair: 1-product
    float* __restrict__ C, const float* __restrict__ src,
    const float* __restrict__ bias0, const float* __restrict__ bias1,
    int M, int N)
{
    __shared__ uint32_t sA[8][136];
    __shared__ uint32_t sB0[8][136];
    __shared__ uint32_t sB1[8][136];

    const int tid = threadIdx.x;
    const int m0 = blockIdx.y * 128;
    const int n0 = blockIdx.x * 128;

    float acc[4][8][4];
    #pragma unroll
    for (int mt = 0; mt < 4; mt++)
        #pragma unroll
        for (int nt = 0; nt < 8; nt++)
            #pragma unroll
            for (int r = 0; r < 4; r++) acc[mt][nt][r] = 0.f;

    gemm_loop2(A1, B10, B11, K1, m0, n0, tid, sA, sB0, sB1, acc);
    if (A2)
        gemm_loop1(A2, B20, K2, m0, n0, tid, sA, sB0, acc);

    // epilogue
    const int lane = tid & 31;
    const int w = tid >> 5;
    const int g = lane >> 2;
    const int t4 = lane & 3;
    const int wm0 = (w >> 1) * 64;
    const int wn0 = (w & 1) * 64;

    #pragma unroll
    for (int nt = 0; nt < 8; nt++) {
        int c = n0 + wn0 + nt * 8 + 2 * t4;
        float add0 = 0.f, add1 = 0.f;
        if (bias0) { add0 += bias0[c]; add1 += bias0[c + 1]; }
        if (bias1) { add0 += bias1[c]; add1 += bias1[c + 1]; }
        #pragma unroll
        for (int mt = 0; mt < 4; mt++) {
            int r0 = m0 + wm0 + mt * 16 + g;
            int r1 = r0 + 8;
            float2 v0 = make_float2(acc[mt][nt][0] + add0, acc[mt][nt][1] + add1);
            float2 v1 = make_float2(acc[mt][nt][2] + add0, acc[mt][nt][3] + add1);
            size_t o0 = (size_t)r0 * N + c;
            size_t o1 = (size_t)r1 * N + c;
            if (src) {
                float2 s0 = *(const float2*)(src + o0);
                float2 s1 = *(const float2*)(src + o1);
                v0.x += s0.x; v0.y += s0.y;
                v1.x += s1.x; v1.y += s1.y;
            }
            *(float2*)(C + o0) = v0;
            *(float2*)(C + o1) = v1;
        }
    }
}

// ---------------------------------------------------------------------------
// Chunked linear scan: state_t = decay*state_{t-1} + u_t
__global__ void __launch_bounds__(256) k_scan1() {
    int c = blockIdx.x, b = blockIdx.y, n = threadIdx.x;
    float d = g_decay[n];
    const float* up = g_u + ((size_t)(b*Ss + c*CHUNK)) * Nn + n;
    float s = 0.f;
    #pragma unroll 8
    for (int t = 0; t < CHUNK; t++) s = fmaf(d, s, up[(size_t)t * Nn]);
    g_loc[(b*NCHUNK + c)*Nn + n] = s;
}

__global__ void k_scan2() {
    int idx = threadIdx.x + blockIdx.x * blockDim.x;   // <<<4,256>>> -> 1024
    int b = idx >> 8, n = idx & 255;
    float dL = g_decayL[n];
    float init = 0.f;
    for (int c = 0; c < NCHUNK; c++) {
        g_init[(b*NCHUNK + c)*Nn + n] = init;
        init = fmaf(dL, init, g_loc[(b*NCHUNK + c)*Nn + n]);
    }
}

// Pass 3: rescan with correct init, write fp16 states
__global__ void __launch_bounds__(256) k_scan3() {
    int c = blockIdx.x, b = blockIdx.y, n = threadIdx.x;
    float d = g_decay[n];
    size_t base = ((size_t)(b*Ss + c*CHUNK)) * Nn + n;
    float s = g_init[(b*NCHUNK + c)*Nn + n];
    #pragma unroll 4
    for (int t = 0; t < CHUNK; t++) {
        s = fmaf(d, s, g_u[base + (size_t)t * Nn]);
        g_th[base + (size_t)t * Nn] = __float2half_rn(s);
    }
}

// ---------------------------------------------------------------------------
extern "C" void kernel_launch(void* const* d_in, const int* in_sizes, int n_in,
                              void* d_out, int out_size)
{
    const float* tokens    = (const float*)d_in[0];
    const float* norm_w    = (const float*)d_in[1];
    const float* W_in      = (const float*)d_in[2];
    const float* b_in      = (const float*)d_in[3];
    const float* W_out     = (const float*)d_in[4];
    const float* b_out     = (const float*)d_in[5];
    const float* W_skip    = (const float*)d_in[6];
    const float* b_skip    = (const float*)d_in[7];
    const float* log_decay = (const float*)d_in[8];
    float* out = (float*)d_out;

    void *p;
    cudaGetSymbolAddress(&p, g_xh);  __half* xh = (__half*)p;
    cudaGetSymbolAddress(&p, g_th);  __half* th = (__half*)p;
    cudaGetSymbolAddress(&p, g_u);   float*  u  = (float*)p;
    cudaGetSymbolAddress(&p, g_wi0); __half* wi0 = (__half*)p;
    cudaGetSymbolAddress(&p, g_wi1); __half* wi1 = (__half*)p;
    cudaGetSymbolAddress(&p, g_wo0); __half* wo0 = (__half*)p;
    cudaGetSymbolAddress(&p, g_wo1); __half* wo1 = (__half*)p;
    cudaGetSymbolAddress(&p, g_ws0); __half* ws0 = (__half*)p;

    // 1) decay precompute + weight splits/converts
    k_decay<<<1, Nn>>>(log_decay);
    k_splitW<<<(Nn*Dd + 255)/256, 256>>>(W_in,   wi0, wi1, Nn*Dd);
    k_splitW<<<(Dd*Nn + 255)/256, 256>>>(W_out,  wo0, wo1, Dd*Nn);
    k_cvtW<<<(Dd*Dd + 255)/256, 256>>>(W_skip, ws0, Dd*Dd);

    // 2) RMSNorm -> fp16 x
    k_rmsnorm<<<Mm, 256>>>(tokens, norm_w);

    // 3) u = x @ W_in^T + b_in   [16384 x 256], K=1024   (2-product)
    {
        dim3 g(Nn/128, Mm/128);
        k_gemmh<<<g, 128>>>(xh, wi0, wi1, Dd,
                            nullptr, nullptr, 0,
                            u, nullptr, b_in, nullptr, Mm, Nn);
    }

    // 4-6) chunked scan -> fp16 states
    {
        dim3 g(NCHUNK, Bb);
        k_scan1<<<g, 256>>>();
        k_scan2<<<4, 256>>>();
        k_scan3<<<g, 256>>>();
    }

    // 7) out = states @ W_out^T (2-prod) + x @ W_skip^T (1-prod)
    //        + tokens + b_out + b_skip
    {
        dim3 g(Dd/128, Mm/128);
        k_gemmh<<<g, 128>>>(th, wo0, wo1, Nn,
                            xh, ws0, Dd,
                            out, tokens, b_out, b_skip, Mm, Dd);
    }
}

// round 10
// speedup vs baseline: 3.6794x; 1.2364x over previous
#include <cuda_runtime.h>
#include <cuda_fp16.h>
#include <math.h>
#include <cstdint>

// Problem dims (fixed for this dataset entry)
#define Bb 4
#define Ss 4096
#define Dd 1024
#define Nn 256
#define Mm (Bb*Ss)            // 16384 tokens
#define CHUNK 64
#define NCHUNK (Ss/CHUNK)     // 64

// Scratch (allocations forbidden -> device globals)
__device__ __half g_xh[(size_t)Mm*Dd];      // 32 MB  x (fp16)
__device__ __half g_th[(size_t)Mm*Nn];      // 8 MB   states (fp16)
__device__ float  g_u[(size_t)Mm*Nn];       // 16 MB  input projection
__device__ __half g_wi0[Nn*Dd];             // W_in  (fp16)
__device__ __half g_wo0[Dd*Nn];             // W_out (fp16)
__device__ __half g_ws0[Dd*Dd];             // W_skip (fp16)
__device__ float  g_loc[Bb*NCHUNK*Nn];
__device__ float  g_init[Bb*NCHUNK*Nn];
__device__ float  g_decay[Nn];
__device__ float  g_decayL[Nn];

// ---------------------------------------------------------------------------
__global__ void k_decay(const float* __restrict__ log_decay) {
    int n = threadIdx.x;
    float d = 1.0f / (1.0f + expf(-log_decay[n]));
    g_decay[n] = d;
    float p = d;
    #pragma unroll
    for (int i = 0; i < 6; i++) p *= p;
    g_decayL[n] = p;
}

// Convert fp32 -> fp16 (vectorized: 4 floats per thread)
__global__ void k_cvtW(const float* __restrict__ src, __half* __restrict__ d0, int n4) {
    int i = blockIdx.x * blockDim.x + threadIdx.x;
    if (i < n4) {
        float4 v = ((const float4*)src)[i];
        __half2* o = (__half2*)d0;
        o[2*i]   = __floats2half2_rn(v.x, v.y);
        o[2*i+1] = __floats2half2_rn(v.z, v.w);
    }
}

// ---------------------------------------------------------------------------
// RMSNorm: one block per token, 256 threads; emits fp16 x
__global__ void __launch_bounds__(256) k_rmsnorm(const float* __restrict__ tokens,
                                                 const float* __restrict__ norm_w) {
    int t = blockIdx.x;
    const float4* tp = (const float4*)(tokens + (size_t)t * Dd);
    float4 v = tp[threadIdx.x];
    float ss = v.x*v.x + v.y*v.y + v.z*v.z + v.w*v.w;
    #pragma unroll
    for (int o = 16; o > 0; o >>= 1) ss += __shfl_xor_sync(0xffffffffu, ss, o);
    __shared__ float wsum[8];
    int wid = threadIdx.x >> 5, lane = threadIdx.x & 31;
    if (lane == 0) wsum[wid] = ss;
    __syncthreads();
    float tot = 0.f;
    #pragma unroll
    for (int i = 0; i < 8; i++) tot += wsum[i];
    float scale = rsqrtf(tot * (1.0f / Dd) + 1e-4f);
    float4 w = ((const float4*)norm_w)[threadIdx.x];
    __half2* ph = (__half2*)(g_xh + (size_t)t * Dd);
    ph[2*threadIdx.x]   = __floats2half2_rn(v.x * scale * w.x, v.y * scale * w.y);
    ph[2*threadIdx.x+1] = __floats2half2_rn(v.z * scale * w.z, v.w * scale * w.w);
}

// ---------------------------------------------------------------------------
// fp16 tensor-core GEMM (single product), ping-pong smem, 1 sync per k-tile.
// C[m,n] = sum_k A[m,k]*B[n,k] (+bias0[n]) (+bias1[n]) (+src[m,n])
// CTA: 128x128 tile, 128 threads = 4 warps (2x2), warp tile 64x64.
// BK=16 -> m16n8k16. Smem [stage][kw][m] pitch 136.

__device__ __forceinline__ void mma_f16(float* d, const uint32_t* a, const uint32_t* b) {
    asm volatile(
        "mma.sync.aligned.m16n8k16.row.col.f32.f16.f16.f32 "
        "{%0,%1,%2,%3},{%4,%5,%6,%7},{%8,%9},{%0,%1,%2,%3};"
        : "+f"(d[0]), "+f"(d[1]), "+f"(d[2]), "+f"(d[3])
        : "r"(a[0]), "r"(a[1]), "r"(a[2]), "r"(a[3]),
          "r"(b[0]), "r"(b[1]));
}

__device__ __forceinline__ void gemm_loop(
    const __half* __restrict__ A, const __half* __restrict__ B, int K,
    int m0, int n0, int tid,
    uint32_t (*sA)[8][136], uint32_t (*sB)[8][136],
    float (&acc)[4][8][4], int& stage)
{
    const int lane = tid & 31;
    const int w = tid >> 5;
    const int g = lane >> 2;
    const int t4 = lane & 3;
    const int wm0 = (w >> 1) * 64;
    const int wn0 = (w & 1) * 64;

    const __half* Ap = A + (size_t)(m0 + tid) * K;
    const __half* Bp = B + (size_t)(n0 + tid) * K;

    uint4 pa[2], pb[2];
    #pragma unroll
    for (int i = 0; i < 2; i++) {
        pa[i] = ((const uint4*)Ap)[i];
        pb[i] = ((const uint4*)Bp)[i];
    }

    for (int k0 = 0; k0 < K; k0 += 16) {
        const int p = stage & 1;
        const uint32_t* wa = (const uint32_t*)pa;
        const uint32_t* wb = (const uint32_t*)pb;
        #pragma unroll
        for (int j = 0; j < 8; j++) {
            sA[p][j][tid] = wa[j];
            sB[p][j][tid] = wb[j];
        }
        __syncthreads();   // single sync per tile (ping-pong keeps prev stage safe)

        if (k0 + 16 < K) {
            const uint4* qa = (const uint4*)(Ap + k0 + 16);
            const uint4* qb = (const uint4*)(Bp + k0 + 16);
            #pragma unroll
            for (int i = 0; i < 2; i++) { pa[i] = qa[i]; pb[i] = qb[i]; }
        }

        uint32_t bf[8][2];
        #pragma unroll
        for (int nt = 0; nt < 8; nt++) {
            int n = wn0 + nt * 8 + g;
            bf[nt][0] = sB[p][t4][n];
            bf[nt][1] = sB[p][t4 + 4][n];
        }
        #pragma unroll
        for (int mt = 0; mt < 4; mt++) {
            int m = wm0 + mt * 16 + g;
            uint32_t af[4] = {sA[p][t4][m], sA[p][t4][m + 8],
                              sA[p][t4 + 4][m], sA[p][t4 + 4][m + 8]};
            #pragma unroll
            for (int nt = 0; nt < 8; nt++)
                mma_f16(acc[mt][nt], af, bf[nt]);
        }
        stage++;
    }
}

__global__ void __launch_bounds__(128) k_gemmh(
    const __half* __restrict__ A1, const __half* __restrict__ B1, int K1,
    const __half* __restrict__ A2, const __half* __restrict__ B2, int K2,
    float* __restrict__ C, const float* __restrict__ src,
    const float* __restrict__ bias0, const float* __restrict__ bias1,
    int M, int N)
{
    __shared__ uint32_t sA[2][8][136];
    __shared__ uint32_t sB[2][8][136];

    const int tid = threadIdx.x;
    const int m0 = blockIdx.y * 128;
    const int n0 = blockIdx.x * 128;

    float acc[4][8][4];
    #pragma unroll
    for (int mt = 0; mt < 4; mt++)
        #pragma unroll
        for (int nt = 0; nt < 8; nt++)
            #pragma unroll
            for (int r = 0; r < 4; r++) acc[mt][nt][r] = 0.f;

    int stage = 0;
    gemm_loop(A1, B1, K1, m0, n0, tid, sA, sB, acc, stage);
    if (A2)
        gemm_loop(A2, B2, K2, m0, n0, tid, sA, sB, acc, stage);

    // epilogue
    const int lane = tid & 31;
    const int w = tid >> 5;
    const int g = lane >> 2;
    const int t4 = lane & 3;
    const int wm0 = (w >> 1) * 64;
    const int wn0 = (w & 1) * 64;

    #pragma unroll
    for (int nt = 0; nt < 8; nt++) {
        int c = n0 + wn0 + nt * 8 + 2 * t4;
        float add0 = 0.f, add1 = 0.f;
        if (bias0) { add0 += bias0[c]; add1 += bias0[c + 1]; }
        if (bias1) { add0 += bias1[c]; add1 += bias1[c + 1]; }
        #pragma unroll
        for (int mt = 0; mt < 4; mt++) {
            int r0 = m0 + wm0 + mt * 16 + g;
            int r1 = r0 + 8;
            float2 v0 = make_float2(acc[mt][nt][0] + add0, acc[mt][nt][1] + add1);
            float2 v1 = make_float2(acc[mt][nt][2] + add0, acc[mt][nt][3] + add1);
            size_t o0 = (size_t)r0 * N + c;
            size_t o1 = (size_t)r1 * N + c;
            if (src) {
                float2 s0 = *(const float2*)(src + o0);
                float2 s1 = *(const float2*)(src + o1);
                v0.x += s0.x; v0.y += s0.y;
                v1.x += s1.x; v1.y += s1.y;
            }
            *(float2*)(C + o0) = v0;
            *(float2*)(C + o1) = v1;
        }
    }
}

// ---------------------------------------------------------------------------
// Chunked linear scan: state_t = decay*state_{t-1} + u_t
__global__ void __launch_bounds__(256) k_scan1() {
    int c = blockIdx.x, b = blockIdx.y, n = threadIdx.x;
    float d = g_decay[n];
    const float* up = g_u + ((size_t)(b*Ss + c*CHUNK)) * Nn + n;
    float s = 0.f;
    #pragma unroll 8
    for (int t = 0; t < CHUNK; t++) s = fmaf(d, s, up[(size_t)t * Nn]);
    g_loc[(b*NCHUNK + c)*Nn + n] = s;
}

__global__ void k_scan2() {
    int idx = threadIdx.x + blockIdx.x * blockDim.x;   // <<<4,256>>> -> 1024
    int b = idx >> 8, n = idx & 255;
    float dL = g_decayL[n];
    float init = 0.f;
    for (int c = 0; c < NCHUNK; c++) {
        g_init[(b*NCHUNK + c)*Nn + n] = init;
        init = fmaf(dL, init, g_loc[(b*NCHUNK + c)*Nn + n]);
    }
}

// Pass 3: rescan with correct init, write fp16 states
__global__ void __launch_bounds__(256) k_scan3() {
    int c = blockIdx.x, b = blockIdx.y, n = threadIdx.x;
    float d = g_decay[n];
    size_t base = ((size_t)(b*Ss + c*CHUNK)) * Nn + n;
    float s = g_init[(b*NCHUNK + c)*Nn + n];
    #pragma unroll 4
    for (int t = 0; t < CHUNK; t++) {
        s = fmaf(d, s, g_u[base + (size_t)t * Nn]);
        g_th[base + (size_t)t * Nn] = __float2half_rn(s);
    }
}

// ---------------------------------------------------------------------------
extern "C" void kernel_launch(void* const* d_in, const int* in_sizes, int n_in,
                              void* d_out, int out_size)
{
    const float* tokens    = (const float*)d_in[0];
    const float* norm_w    = (const float*)d_in[1];
    const float* W_in      = (const float*)d_in[2];
    const float* b_in      = (const float*)d_in[3];
    const float* W_out     = (const float*)d_in[4];
    const float* b_out     = (const float*)d_in[5];
    const float* W_skip    = (const float*)d_in[6];
    const float* b_skip    = (const float*)d_in[7];
    const float* log_decay = (const float*)d_in[8];
    float* out = (float*)d_out;

    void *p;
    cudaGetSymbolAddress(&p, g_xh);  __half* xh = (__half*)p;
    cudaGetSymbolAddress(&p, g_th);  __half* th = (__half*)p;
    cudaGetSymbolAddress(&p, g_u);   float*  u  = (float*)p;
    cudaGetSymbolAddress(&p, g_wi0); __half* wi0 = (__half*)p;
    cudaGetSymbolAddress(&p, g_wo0); __half* wo0 = (__half*)p;
    cudaGetSymbolAddress(&p, g_ws0); __half* ws0 = (__half*)p;

    // 1) decay precompute + weight converts (all fp16 single product)
    k_decay<<<1, Nn>>>(log_decay);
    k_cvtW<<<(Nn*Dd/4 + 255)/256, 256>>>(W_in,   wi0, Nn*Dd/4);
    k_cvtW<<<(Dd*Nn/4 + 255)/256, 256>>>(W_out,  wo0, Dd*Nn/4);
    k_cvtW<<<(Dd*Dd/4 + 255)/256, 256>>>(W_skip, ws0, Dd*Dd/4);

    // 2) RMSNorm -> fp16 x
    k_rmsnorm<<<Mm, 256>>>(tokens, norm_w);

    // 3) u = x @ W_in^T + b_in   [16384 x 256], K=1024
    {
        dim3 g(Nn/128, Mm/128);
        k_gemmh<<<g, 128>>>(xh, wi0, Dd,
                            nullptr, nullptr, 0,
                            u, nullptr, b_in, nullptr, Mm, Nn);
    }

    // 4-6) chunked scan -> fp16 states
    {
        dim3 g(NCHUNK, Bb);
        k_scan1<<<g, 256>>>();
        k_scan2<<<4, 256>>>();
        k_scan3<<<g, 256>>>();
    }

    // 7) out = states @ W_out^T + x @ W_skip^T + tokens + b_out + b_skip
    {
        dim3 g(Dd/128, Mm/128);
        k_gemmh<<<g, 128>>>(th, wo0, Nn,
                            xh, ws0, Dd,
                            out, tokens, b_out, b_skip, Mm, Dd);
    }
}

// round 12
// speedup vs baseline: 3.7348x; 1.0151x over previous
#include <cuda_runtime.h>
#include <cuda_fp16.h>
#include <math.h>
#include <cstdint>

// Problem dims (fixed for this dataset entry)
#define Bb 4
#define Ss 4096
#define Dd 1024
#define Nn 256
#define Mm (Bb*Ss)            // 16384 tokens
#define CHUNK 64
#define NCHUNK (Ss/CHUNK)     // 64

// Scratch (allocations forbidden -> device globals)
__device__ __half g_xh[(size_t)Mm*Dd];      // 32 MB  x (fp16)
__device__ __half g_th[(size_t)Mm*Nn];      // 8 MB   states (fp16)
__device__ float  g_u[(size_t)Mm*Nn];       // 16 MB  input projection
__device__ __half g_wi0[Nn*Dd];             // W_in  (fp16)
__device__ __half g_wo0[Dd*Nn];             // W_out (fp16)
__device__ __half g_ws0[Dd*Dd];             // W_skip (fp16)
__device__ float  g_loc[Bb*NCHUNK*Nn];
__device__ float  g_init[Bb*NCHUNK*Nn];
__device__ float  g_decay[Nn];
__device__ float  g_decayL[Nn];

// ---------------------------------------------------------------------------
__global__ void k_decay(const float* __restrict__ log_decay) {
    int n = threadIdx.x;
    float d = 1.0f / (1.0f + expf(-log_decay[n]));
    g_decay[n] = d;
    float p = d;
    #pragma unroll
    for (int i = 0; i < 6; i++) p *= p;
    g_decayL[n] = p;
}

// Convert fp32 -> fp16 (vectorized: 4 floats per thread)
__global__ void k_cvtW(const float* __restrict__ src, __half* __restrict__ d0, int n4) {
    int i = blockIdx.x * blockDim.x + threadIdx.x;
    if (i < n4) {
        float4 v = ((const float4*)src)[i];
        __half2* o = (__half2*)d0;
        o[2*i]   = __floats2half2_rn(v.x, v.y);
        o[2*i+1] = __floats2half2_rn(v.z, v.w);
    }
}

// ---------------------------------------------------------------------------
// RMSNorm: one block per token, 256 threads; emits fp16 x
__global__ void __launch_bounds__(256) k_rmsnorm(const float* __restrict__ tokens,
                                                 const float* __restrict__ norm_w) {
    int t = blockIdx.x;
    const float4* tp = (const float4*)(tokens + (size_t)t * Dd);
    float4 v = tp[threadIdx.x];
    float ss = v.x*v.x + v.y*v.y + v.z*v.z + v.w*v.w;
    #pragma unroll
    for (int o = 16; o > 0; o >>= 1) ss += __shfl_xor_sync(0xffffffffu, ss, o);
    __shared__ float wsum[8];
    int wid = threadIdx.x >> 5, lane = threadIdx.x & 31;
    if (lane == 0) wsum[wid] = ss;
    __syncthreads();
    float tot = 0.f;
    #pragma unroll
    for (int i = 0; i < 8; i++) tot += wsum[i];
    float scale = rsqrtf(tot * (1.0f / Dd) + 1e-4f);
    float4 w = ((const float4*)norm_w)[threadIdx.x];
    __half2* ph = (__half2*)(g_xh + (size_t)t * Dd);
    ph[2*threadIdx.x]   = __floats2half2_rn(v.x * scale * w.x, v.y * scale * w.y);
    ph[2*threadIdx.x+1] = __floats2half2_rn(v.z * scale * w.z, v.w * scale * w.w);
}

// ---------------------------------------------------------------------------
// fp16 tensor-core GEMM (single product), ldmatrix layout, ping-pong smem.
// C[m,n] = sum_k A[m,k]*B[n,k] (+bias0[n]) (+bias1[n]) (+src[m,n])
// CTA: 128x128 tile, 128 threads = 4 warps (2x2), warp tile 64x64.
// BK=16. Smem tile: 128 rows x 32B (16 fp16), 16B-chunk swizzle:
//   phys_chunk = chunk ^ ((row>>2)&1)  -> conflict-free STS.128 and LDSM.

__device__ __forceinline__ void mma_f16(float* d, const uint32_t* a, const uint32_t* b) {
    asm volatile(
        "mma.sync.aligned.m16n8k16.row.col.f32.f16.f16.f32 "
        "{%0,%1,%2,%3},{%4,%5,%6,%7},{%8,%9},{%0,%1,%2,%3};"
        : "+f"(d[0]), "+f"(d[1]), "+f"(d[2]), "+f"(d[3])
        : "r"(a[0]), "r"(a[1]), "r"(a[2]), "r"(a[3]),
          "r"(b[0]), "r"(b[1]));
}

__device__ __forceinline__ void ldsm4(uint32_t* r, uint32_t addr) {
    asm volatile("ldmatrix.sync.aligned.m8n8.x4.shared.b16 {%0,%1,%2,%3}, [%4];"
        : "=r"(r[0]), "=r"(r[1]), "=r"(r[2]), "=r"(r[3]) : "r"(addr));
}

__device__ __forceinline__ int swz_off(int row, int chunk) {
    return row * 32 + ((chunk ^ ((row >> 2) & 1)) * 16);
}

__device__ __forceinline__ void gemm_loop(
    const __half* __restrict__ A, const __half* __restrict__ B, int K,
    int m0, int n0, int tid,
    uint8_t (*smA)[4096], uint8_t (*smB)[4096],
    uint32_t uA, uint32_t uB,
    const int (&offA)[4], const int (&offB)[4],
    int sts0, int sts1,
    float (&acc)[4][8][4], int& stage)
{
    const __half* Ap = A + (size_t)(m0 + tid) * K;
    const __half* Bp = B + (size_t)(n0 + tid) * K;

    uint4 pa0 = ((const uint4*)Ap)[0], pa1 = ((const uint4*)Ap)[1];
    uint4 pb0 = ((const uint4*)Bp)[0], pb1 = ((const uint4*)Bp)[1];

    for (int k0 = 0; k0 < K; k0 += 16) {
        const int p = stage & 1;
        // STS.128 x4 (swizzled row-major tile)
        *(uint4*)(smA[p] + sts0) = pa0;
        *(uint4*)(smA[p] + sts1) = pa1;
        *(uint4*)(smB[p] + sts0) = pb0;
        *(uint4*)(smB[p] + sts1) = pb1;
        __syncthreads();   // single sync per tile (ping-pong protects prev stage)

        if (k0 + 16 < K) {
            const uint4* qa = (const uint4*)(Ap + k0 + 16);
            const uint4* qb = (const uint4*)(Bp + k0 + 16);
            pa0 = qa[0]; pa1 = qa[1];
            pb0 = qb[0]; pb1 = qb[1];
        }

        const uint32_t aA = uA + p * 4096;
        const uint32_t aB = uB + p * 4096;

        uint32_t bfr[4][4];
        #pragma unroll
        for (int ntp = 0; ntp < 4; ntp++)
            ldsm4(bfr[ntp], aB + offB[ntp]);

        #pragma unroll
        for (int mt = 0; mt < 4; mt++) {
            uint32_t afr[4];
            ldsm4(afr, aA + offA[mt]);
            #pragma unroll
            for (int nt = 0; nt < 8; nt++)
                mma_f16(acc[mt][nt], afr, &bfr[nt >> 1][(nt & 1) * 2]);
        }
        stage++;
    }
}

__global__ void __launch_bounds__(128) k_gemmh(
    const __half* __restrict__ A1, const __half* __restrict__ B1, int K1,
    const __half* __restrict__ A2, const __half* __restrict__ B2, int K2,
    float* __restrict__ C, const float* __restrict__ src,
    const float* __restrict__ bias0, const float* __restrict__ bias1,
    int M, int N)
{
    __shared__ __align__(16) uint8_t smA[2][4096];
    __shared__ __align__(16) uint8_t smB[2][4096];

    const int tid = threadIdx.x;
    const int lane = tid & 31;
    const int w = tid >> 5;
    const int wm0 = (w >> 1) * 64;
    const int wn0 = (w & 1) * 64;
    const int m0 = blockIdx.y * 128;
    const int n0 = blockIdx.x * 128;

    const uint32_t uA = (uint32_t)__cvta_generic_to_shared(smA);
    const uint32_t uB = (uint32_t)__cvta_generic_to_shared(smB);

    // ldmatrix per-lane offsets.
    // A, tile mt (m16k16): mats (m,k0)(m+8,k0)(m,k8)(m+8,k8) = a0,a1,a2,a3
    int offA[4], offB[4];
    {
        int r8 = lane & 7;
        int msel = (lane >> 3) & 1;   // +8 rows for mats 1,3
        int csel = (lane >> 4) & 1;   // chunk 1 for mats 2,3
        #pragma unroll
        for (int mt = 0; mt < 4; mt++) {
            int row = wm0 + mt * 16 + r8 + msel * 8;
            offA[mt] = swz_off(row, csel);
        }
        // B, pair ntp (two n8k16 tiles): mats (n,k0)(n,k8)(n+8,k0)(n+8,k8)
        int nsel = (lane >> 4) & 1;   // +8 rows for mats 2,3
        int bcsel = (lane >> 3) & 1;  // chunk 1 for mats 1,3
        #pragma unroll
        for (int ntp = 0; ntp < 4; ntp++) {
            int row = wn0 + ntp * 16 + r8 + nsel * 8;
            offB[ntp] = swz_off(row, bcsel);
        }
    }
    const int sts0 = swz_off(tid, 0);
    const int sts1 = swz_off(tid, 1);

    float acc[4][8][4];
    #pragma unroll
    for (int mt = 0; mt < 4; mt++)
        #pragma unroll
        for (int nt = 0; nt < 8; nt++)
            #pragma unroll
            for (int r = 0; r < 4; r++) acc[mt][nt][r] = 0.f;

    int stage = 0;
    gemm_loop(A1, B1, K1, m0, n0, tid, smA, smB, uA, uB, offA, offB, sts0, sts1, acc, stage);
    if (A2)
        gemm_loop(A2, B2, K2, m0, n0, tid, smA, smB, uA, uB, offA, offB, sts0, sts1, acc, stage);

    // epilogue
    const int g = lane >> 2;
    const int t4 = lane & 3;

    #pragma unroll
    for (int nt = 0; nt < 8; nt++) {
        int c = n0 + wn0 + nt * 8 + 2 * t4;
        float add0 = 0.f, add1 = 0.f;
        if (bias0) { add0 += bias0[c]; add1 += bias0[c + 1]; }
        if (bias1) { add0 += bias1[c]; add1 += bias1[c + 1]; }
        #pragma unroll
        for (int mt = 0; mt < 4; mt++) {
            int r0 = m0 + wm0 + mt * 16 + g;
            int r1 = r0 + 8;
            float2 v0 = make_float2(acc[mt][nt][0] + add0, acc[mt][nt][1] + add1);
            float2 v1 = make_float2(acc[mt][nt][2] + add0, acc[mt][nt][3] + add1);
            size_t o0 = (size_t)r0 * N + c;
            size_t o1 = (size_t)r1 * N + c;
            if (src) {
                float2 s0 = *(const float2*)(src + o0);
                float2 s1 = *(const float2*)(src + o1);
                v0.x += s0.x; v0.y += s0.y;
                v1.x += s1.x; v1.y += s1.y;
            }
            *(float2*)(C + o0) = v0;
            *(float2*)(C + o1) = v1;
        }
    }
}

// ---------------------------------------------------------------------------
// Chunked linear scan: state_t = decay*state_{t-1} + u_t
__global__ void __launch_bounds__(256) k_scan1() {
    int c = blockIdx.x, b = blockIdx.y, n = threadIdx.x;
    float d = g_decay[n];
    const float* up = g_u + ((size_t)(b*Ss + c*CHUNK)) * Nn + n;
    float s = 0.f;
    #pragma unroll 8
    for (int t = 0; t < CHUNK; t++) s = fmaf(d, s, up[(size_t)t * Nn]);
    g_loc[(b*NCHUNK + c)*Nn + n] = s;
}

__global__ void k_scan2() {
    int idx = threadIdx.x + blockIdx.x * blockDim.x;   // <<<4,256>>> -> 1024
    int b = idx >> 8, n = idx & 255;
    float dL = g_decayL[n];
    float init = 0.f;
    for (int c = 0; c < NCHUNK; c++) {
        g_init[(b*NCHUNK + c)*Nn + n] = init;
        init = fmaf(dL, init, g_loc[(b*NCHUNK + c)*Nn + n]);
    }
}

// Pass 3: rescan with correct init, write fp16 states
__global__ void __launch_bounds__(256) k_scan3() {
    int c = blockIdx.x, b = blockIdx.y, n = threadIdx.x;
    float d = g_decay[n];
    size_t base = ((size_t)(b*Ss + c*CHUNK)) * Nn + n;
    float s = g_init[(b*NCHUNK + c)*Nn + n];
    #pragma unroll 4
    for (int t = 0; t < CHUNK; t++) {
        s = fmaf(d, s, g_u[base + (size_t)t * Nn]);
        g_th[base + (size_t)t * Nn] = __float2half_rn(s);
    }
}

// ---------------------------------------------------------------------------
extern "C" void kernel_launch(void* const* d_in, const int* in_sizes, int n_in,
                              void* d_out, int out_size)
{
    const float* tokens    = (const float*)d_in[0];
    const float* norm_w    = (const float*)d_in[1];
    const float* W_in      = (const float*)d_in[2];
    const float* b_in      = (const float*)d_in[3];
    const float* W_out     = (const float*)d_in[4];
    const float* b_out     = (const float*)d_in[5];
    const float* W_skip    = (const float*)d_in[6];
    const float* b_skip    = (const float*)d_in[7];
    const float* log_decay = (const float*)d_in[8];
    float* out = (float*)d_out;

    void *p;
    cudaGetSymbolAddress(&p, g_xh);  __half* xh = (__half*)p;
    cudaGetSymbolAddress(&p, g_th);  __half* th = (__half*)p;
    cudaGetSymbolAddress(&p, g_u);   float*  u  = (float*)p;
    cudaGetSymbolAddress(&p, g_wi0); __half* wi0 = (__half*)p;
    cudaGetSymbolAddress(&p, g_wo0); __half* wo0 = (__half*)p;
    cudaGetSymbolAddress(&p, g_ws0); __half* ws0 = (__half*)p;

    // 1) decay precompute + weight converts
    k_decay<<<1, Nn>>>(log_decay);
    k_cvtW<<<(Nn*Dd/4 + 255)/256, 256>>>(W_in,   wi0, Nn*Dd/4);
    k_cvtW<<<(Dd*Nn/4 + 255)/256, 256>>>(W_out,  wo0, Dd*Nn/4);
    k_cvtW<<<(Dd*Dd/4 + 255)/256, 256>>>(W_skip, ws0, Dd*Dd/4);

    // 2) RMSNorm -> fp16 x
    k_rmsnorm<<<Mm, 256>>>(tokens, norm_w);

    // 3) u = x @ W_in^T + b_in   [16384 x 256], K=1024
    {
        dim3 g(Nn/128, Mm/128);
        k_gemmh<<<g, 128>>>(xh, wi0, Dd,
                            nullptr, nullptr, 0,
                            u, nullptr, b_in, nullptr, Mm, Nn);
    }

    // 4-6) chunked scan -> fp16 states
    {
        dim3 g(NCHUNK, Bb);
        k_scan1<<<g, 256>>>();
        k_scan2<<<4, 256>>>();
        k_scan3<<<g, 256>>>();
    }

    // 7) out = states @ W_out^T + x @ W_skip^T + tokens + b_out + b_skip
    {
        dim3 g(Dd/128, Mm/128);
        k_gemmh<<<g, 128>>>(th, wo0, Nn,
                            xh, ws0, Dd,
                            out, tokens, b_out, b_skip, Mm, Dd);
    }
}

// round 13
// speedup vs baseline: 4.1039x; 1.0988x over previous
#include <cuda_runtime.h>
#include <cuda_fp16.h>
#include <math.h>
#include <cstdint>

// Problem dims (fixed for this dataset entry)
#define Bb 4
#define Ss 4096
#define Dd 1024
#define Nn 256
#define Mm (Bb*Ss)            // 16384 tokens
#define CHUNK 64
#define NCHUNK (Ss/CHUNK)     // 64

// Scratch (allocations forbidden -> device globals)
__device__ __half g_xh[(size_t)Mm*Dd];      // 32 MB  x (fp16)
__device__ __half g_th[(size_t)Mm*Nn];      // 8 MB   states (fp16)
__device__ float  g_u[(size_t)Mm*Nn];       // 16 MB  input projection
__device__ __half g_wi0[Nn*Dd];             // W_in  (fp16)
__device__ __half g_wo0[Dd*Nn];             // W_out (fp16)
__device__ __half g_ws0[Dd*Dd];             // W_skip (fp16)
__device__ float  g_loc[Bb*NCHUNK*Nn];
__device__ float  g_init[Bb*NCHUNK*Nn];
__device__ float  g_decay[Nn];
__device__ float  g_decayL[Nn];

// ---------------------------------------------------------------------------
__global__ void k_decay(const float* __restrict__ log_decay) {
    int n = threadIdx.x;
    float d = 1.0f / (1.0f + expf(-log_decay[n]));
    g_decay[n] = d;
    float p = d;
    #pragma unroll
    for (int i = 0; i < 6; i++) p *= p;
    g_decayL[n] = p;
}

// Convert fp32 -> fp16 (vectorized: 4 floats per thread)
__global__ void k_cvtW(const float* __restrict__ src, __half* __restrict__ d0, int n4) {
    int i = blockIdx.x * blockDim.x + threadIdx.x;
    if (i < n4) {
        float4 v = ((const float4*)src)[i];
        __half2* o = (__half2*)d0;
        o[2*i]   = __floats2half2_rn(v.x, v.y);
        o[2*i+1] = __floats2half2_rn(v.z, v.w);
    }
}

// ---------------------------------------------------------------------------
// RMSNorm: one block per token, 256 threads; emits fp16 x
__global__ void __launch_bounds__(256) k_rmsnorm(const float* __restrict__ tokens,
                                                 const float* __restrict__ norm_w) {
    int t = blockIdx.x;
    const float4* tp = (const float4*)(tokens + (size_t)t * Dd);
    float4 v = tp[threadIdx.x];
    float ss = v.x*v.x + v.y*v.y + v.z*v.z + v.w*v.w;
    #pragma unroll
    for (int o = 16; o > 0; o >>= 1) ss += __shfl_xor_sync(0xffffffffu, ss, o);
    __shared__ float wsum[8];
    int wid = threadIdx.x >> 5, lane = threadIdx.x & 31;
    if (lane == 0) wsum[wid] = ss;
    __syncthreads();
    float tot = 0.f;
    #pragma unroll
    for (int i = 0; i < 8; i++) tot += wsum[i];
    float scale = rsqrtf(tot * (1.0f / Dd) + 1e-4f);
    float4 w = ((const float4*)norm_w)[threadIdx.x];
    __half2* ph = (__half2*)(g_xh + (size_t)t * Dd);
    ph[2*threadIdx.x]   = __floats2half2_rn(v.x * scale * w.x, v.y * scale * w.y);
    ph[2*threadIdx.x+1] = __floats2half2_rn(v.z * scale * w.z, v.w * scale * w.w);
}

// ---------------------------------------------------------------------------
// fp16 tensor-core GEMM, cp.async 3-stage pipeline, BK=32, ldmatrix.
// C[m,n] = sum_k A[m,k]*B[n,k] (+bias0[n]) (+bias1[n]) (+src[m,n])
// Fused second product (A2,B2,K2) continues the same k-tile pipeline.
// CTA: 128x128 tile, 128 threads = 4 warps (2x2), warp tile 64x64.
// Stage = 2 subtiles of the proven layout: 128 rows x 32B, 16B-chunk swizzle
//   phys_chunk = chunk ^ ((row>>2)&1)  -> conflict-free STS(cp.async) + LDSM.

__device__ __forceinline__ void mma_f16(float* d, const uint32_t* a, const uint32_t* b) {
    asm volatile(
        "mma.sync.aligned.m16n8k16.row.col.f32.f16.f16.f32 "
        "{%0,%1,%2,%3},{%4,%5,%6,%7},{%8,%9},{%0,%1,%2,%3};"
        : "+f"(d[0]), "+f"(d[1]), "+f"(d[2]), "+f"(d[3])
        : "r"(a[0]), "r"(a[1]), "r"(a[2]), "r"(a[3]),
          "r"(b[0]), "r"(b[1]));
}

__device__ __forceinline__ void ldsm4(uint32_t* r, uint32_t addr) {
    asm volatile("ldmatrix.sync.aligned.m8n8.x4.shared.b16 {%0,%1,%2,%3}, [%4];"
        : "=r"(r[0]), "=r"(r[1]), "=r"(r[2]), "=r"(r[3]) : "r"(addr));
}

__device__ __forceinline__ void cp16(uint32_t saddr, const void* gaddr) {
    asm volatile("cp.async.cg.shared.global [%0], [%1], 16;" :: "r"(saddr), "l"(gaddr));
}
#define CP_COMMIT() asm volatile("cp.async.commit_group;" ::: "memory")
#define CP_WAIT1()  asm volatile("cp.async.wait_group 1;" ::: "memory")

__device__ __forceinline__ int swz_off(int row, int chunk) {
    return row * 32 + ((chunk ^ ((row >> 2) & 1)) * 16);
}

#define NSTAGE 3
#define STAGEB 8192   // per operand per stage: 2 subtiles x 4096B

__global__ void __launch_bounds__(128) k_gemmh(
    const __half* __restrict__ A1, const __half* __restrict__ B1, int K1,
    const __half* __restrict__ A2, const __half* __restrict__ B2, int K2,
    float* __restrict__ C, const float* __restrict__ src,
    const float* __restrict__ bias0, const float* __restrict__ bias1,
    int M, int N)
{
    __shared__ __align__(16) uint8_t smA[NSTAGE][STAGEB];
    __shared__ __align__(16) uint8_t smB[NSTAGE][STAGEB];

    const int tid = threadIdx.x;
    const int lane = tid & 31;
    const int w = tid >> 5;
    const int wm0 = (w >> 1) * 64;
    const int wn0 = (w & 1) * 64;
    const int m0 = blockIdx.y * 128;
    const int n0 = blockIdx.x * 128;

    const uint32_t uA = (uint32_t)__cvta_generic_to_shared(smA);
    const uint32_t uB = (uint32_t)__cvta_generic_to_shared(smB);

    // ldmatrix per-lane offsets (within one 4KB subtile).
    int offA[4], offB[4];
    {
        int r8 = lane & 7;
        int msel = (lane >> 3) & 1;   // A: +8 rows for mats 1,3
        int csel = (lane >> 4) & 1;   // A: chunk 1 for mats 2,3
        #pragma unroll
        for (int mt = 0; mt < 4; mt++)
            offA[mt] = swz_off(wm0 + mt * 16 + r8 + msel * 8, csel);
        int nsel = (lane >> 4) & 1;   // B: +8 rows for mats 2,3
        int bcsel = (lane >> 3) & 1;  // B: chunk 1 for mats 1,3
        #pragma unroll
        for (int ntp = 0; ntp < 4; ntp++)
            offB[ntp] = swz_off(wn0 + ntp * 16 + r8 + nsel * 8, bcsel);
    }
    const int stsw0 = swz_off(tid, 0);
    const int stsw1 = swz_off(tid, 1);

    // per-thread global row pointers for both products
    const __half* A1p = A1 + (size_t)(m0 + tid) * K1;
    const __half* B1p = B1 + (size_t)(n0 + tid) * K1;
    const __half* A2p = A2 ? A2 + (size_t)(m0 + tid) * K2 : nullptr;
    const __half* B2p = A2 ? B2 + (size_t)(n0 + tid) * K2 : nullptr;

    const int t1 = K1 / 32;
    const int T = t1 + (A2 ? K2 / 32 : 0);

    // issue async loads for k-tile i into slot i % NSTAGE
    auto issue = [&](int i) {
        const int slot = i % NSTAGE;
        const uint32_t dA = uA + slot * STAGEB;
        const uint32_t dB = uB + slot * STAGEB;
        const __half *ap, *bp; int k0;
        if (i < t1) { ap = A1p; bp = B1p; k0 = i * 32; }
        else        { ap = A2p; bp = B2p; k0 = (i - t1) * 32; }
        #pragma unroll
        for (int s = 0; s < 2; s++) {
            cp16(dA + s * 4096 + stsw0, ap + k0 + s * 16);
            cp16(dA + s * 4096 + stsw1, ap + k0 + s * 16 + 8);
            cp16(dB + s * 4096 + stsw0, bp + k0 + s * 16);
            cp16(dB + s * 4096 + stsw1, bp + k0 + s * 16 + 8);
        }
        CP_COMMIT();
    };

    float acc[4][8][4];
    #pragma unroll
    for (int mt = 0; mt < 4; mt++)
        #pragma unroll
        for (int nt = 0; nt < 8; nt++)
            #pragma unroll
            for (int r = 0; r < 4; r++) acc[mt][nt][r] = 0.f;

    issue(0);
    issue(1);

    for (int i = 0; i < T; i++) {
        CP_WAIT1();          // tile i resident (<=1 group pending)
        __syncthreads();     // all warps past compute(i-1): slot (i+2)%3 is free
        if (i + 2 < T) issue(i + 2);

        const int slot = i % NSTAGE;
        #pragma unroll
        for (int s = 0; s < 2; s++) {
            const uint32_t aA = uA + slot * STAGEB + s * 4096;
            const uint32_t aB = uB + slot * STAGEB + s * 4096;
            uint32_t bfr[4][4];
            #pragma unroll
            for (int ntp = 0; ntp < 4; ntp++)
                ldsm4(bfr[ntp], aB + offB[ntp]);
            #pragma unroll
            for (int mt = 0; mt < 4; mt++) {
                uint32_t afr[4];
                ldsm4(afr, aA + offA[mt]);
                #pragma unroll
                for (int nt = 0; nt < 8; nt++)
                    mma_f16(acc[mt][nt], afr, &bfr[nt >> 1][(nt & 1) * 2]);
            }
        }
    }

    // epilogue
    const int g = lane >> 2;
    const int t4 = lane & 3;

    #pragma unroll
    for (int nt = 0; nt < 8; nt++) {
        int c = n0 + wn0 + nt * 8 + 2 * t4;
        float add0 = 0.f, add1 = 0.f;
        if (bias0) { add0 += bias0[c]; add1 += bias0[c + 1]; }
        if (bias1) { add0 += bias1[c]; add1 += bias1[c + 1]; }
        #pragma unroll
        for (int mt = 0; mt < 4; mt++) {
            int r0 = m0 + wm0 + mt * 16 + g;
            int r1 = r0 + 8;
            float2 v0 = make_float2(acc[mt][nt][0] + add0, acc[mt][nt][1] + add1);
            float2 v1 = make_float2(acc[mt][nt][2] + add0, acc[mt][nt][3] + add1);
            size_t o0 = (size_t)r0 * N + c;
            size_t o1 = (size_t)r1 * N + c;
            if (src) {
                float2 s0 = *(const float2*)(src + o0);
                float2 s1 = *(const float2*)(src + o1);
                v0.x += s0.x; v0.y += s0.y;
                v1.x += s1.x; v1.y += s1.y;
            }
            *(float2*)(C + o0) = v0;
            *(float2*)(C + o1) = v1;
        }
    }
}

// ---------------------------------------------------------------------------
// Chunked linear scan: state_t = decay*state_{t-1} + u_t
__global__ void __launch_bounds__(256) k_scan1() {
    int c = blockIdx.x, b = blockIdx.y, n = threadIdx.x;
    float d = g_decay[n];
    const float* up = g_u + ((size_t)(b*Ss + c*CHUNK)) * Nn + n;
    float s = 0.f;
    #pragma unroll 8
    for (int t = 0; t < CHUNK; t++) s = fmaf(d, s, up[(size_t)t * Nn]);
    g_loc[(b*NCHUNK + c)*Nn + n] = s;
}

__global__ void k_scan2() {
    int idx = threadIdx.x + blockIdx.x * blockDim.x;   // <<<4,256>>> -> 1024
    int b = idx >> 8, n = idx & 255;
    float dL = g_decayL[n];
    float init = 0.f;
    for (int c = 0; c < NCHUNK; c++) {
        g_init[(b*NCHUNK + c)*Nn + n] = init;
        init = fmaf(dL, init, g_loc[(b*NCHUNK + c)*Nn + n]);
    }
}

// Pass 3: rescan with correct init, write fp16 states
__global__ void __launch_bounds__(256) k_scan3() {
    int c = blockIdx.x, b = blockIdx.y, n = threadIdx.x;
    float d = g_decay[n];
    size_t base = ((size_t)(b*Ss + c*CHUNK)) * Nn + n;
    float s = g_init[(b*NCHUNK + c)*Nn + n];
    #pragma unroll 4
    for (int t = 0; t < CHUNK; t++) {
        s = fmaf(d, s, g_u[base + (size_t)t * Nn]);
        g_th[base + (size_t)t * Nn] = __float2half_rn(s);
    }
}

// ---------------------------------------------------------------------------
extern "C" void kernel_launch(void* const* d_in, const int* in_sizes, int n_in,
                              void* d_out, int out_size)
{
    const float* tokens    = (const float*)d_in[0];
    const float* norm_w    = (const float*)d_in[1];
    const float* W_in      = (const float*)d_in[2];
    const float* b_in      = (const float*)d_in[3];
    const float* W_out     = (const float*)d_in[4];
    const float* b_out     = (const float*)d_in[5];
    const float* W_skip    = (const float*)d_in[6];
    const float* b_skip    = (const float*)d_in[7];
    const float* log_decay = (const float*)d_in[8];
    float* out = (float*)d_out;

    void *p;
    cudaGetSymbolAddress(&p, g_xh);  __half* xh = (__half*)p;
    cudaGetSymbolAddress(&p, g_th);  __half* th = (__half*)p;
    cudaGetSymbolAddress(&p, g_u);   float*  u  = (float*)p;
    cudaGetSymbolAddress(&p, g_wi0); __half* wi0 = (__half*)p;
    cudaGetSymbolAddress(&p, g_wo0); __half* wo0 = (__half*)p;
    cudaGetSymbolAddress(&p, g_ws0); __half* ws0 = (__half*)p;

    // 1) decay precompute + weight converts
    k_decay<<<1, Nn>>>(log_decay);
    k_cvtW<<<(Nn*Dd/4 + 255)/256, 256>>>(W_in,   wi0, Nn*Dd/4);
    k_cvtW<<<(Dd*Nn/4 + 255)/256, 256>>>(W_out,  wo0, Dd*Nn/4);
    k_cvtW<<<(Dd*Dd/4 + 255)/256, 256>>>(W_skip, ws0, Dd*Dd/4);

    // 2) RMSNorm -> fp16 x
    k_rmsnorm<<<Mm, 256>>>(tokens, norm_w);

    // 3) u = x @ W_in^T + b_in   [16384 x 256], K=1024
    {
        dim3 g(Nn/128, Mm/128);
        k_gemmh<<<g, 128>>>(xh, wi0, Dd,
                            nullptr, nullptr, 0,
                            u, nullptr, b_in, nullptr, Mm, Nn);
    }

    // 4-6) chunked scan -> fp16 states
    {
        dim3 g(NCHUNK, Bb);
        k_scan1<<<g, 256>>>();
        k_scan2<<<4, 256>>>();
        k_scan3<<<g, 256>>>();
    }

    // 7) out = states @ W_out^T + x @ W_skip^T + tokens + b_out + b_skip
    {
        dim3 g(Dd/128, Mm/128);
        k_gemmh<<<g, 128>>>(th, wo0, Nn,
                            xh, ws0, Dd,
                            out, tokens, b_out, b_skip, Mm, Dd);
    }
}